// round 10
// baseline (speedup 1.0000x reference)
#include <cuda_runtime.h>
#include <math.h>
#include <stdint.h>

#define NN 30000
#define TT 4
#define FIN 256
#define HH 64
#define HEADS 4
#define DD 256
#define EE 240000
#define ETOT 270000            // EE + NN self loops
#define NEG_SLOPE 0.2f
#define NB_SCAN 118            // ceil(NN/256)
#define ESZ (TT * NN * HEADS)

// ---------------- scratch (device globals: allocation-free) ----------------
__device__ __align__(16) float g_h0[TT * NN * HH];     // xWp output (incl bp), (t,n) order
__device__ __align__(16) float g_hp[TT * NN * DD];     // layer0: agg0 (head-major); layer1: hp1
__device__ __align__(16) float g_bufA[TT * NN * DD];   // layer0 output (post ELU)
__device__ __align__(16) float g_bufB[TT * NN * DD];   // layer1 output (embs)
__device__ __align__(16) float g_esed[2 * ESZ];        // es at 0, ed at ESZ
__device__ __align__(16) float g_colsum[TT * DD];
__device__ __align__(16) float g_avs[HH * HEADS];      // (W0 . a_src0): av[k][h]
__device__ __align__(16) float g_avd[HH * HEADS];
__device__ float g_attn[TT];
// CSR
__device__ int g_deg[NN];
__device__ int g_off[NN];
__device__ int g_cursor[NN];
__device__ int g_part[256];
__device__ int g_srcs[ETOT];

// ---------------- utility ----------------
__global__ void zero_kernel(float4* __restrict__ p, int n4) {
    int i = blockIdx.x * blockDim.x + threadIdx.x;
    if (i < n4) p[i] = make_float4(0.f, 0.f, 0.f, 0.f);
}

__device__ __forceinline__ float eluf(float x) { return x > 0.f ? x : expm1f(x); }

__device__ __forceinline__ uint32_t f2tf32(float x) {
    uint32_t r;
    asm("cvt.rna.tf32.f32 %0, %1;" : "=r"(r) : "f"(x));
    return r;
}

__device__ __forceinline__ void mma_tf32(float* c, const uint32_t* a, const uint32_t* b) {
    asm volatile(
        "mma.sync.aligned.m16n8k8.row.col.f32.tf32.tf32.f32 "
        "{%0,%1,%2,%3}, {%4,%5,%6,%7}, {%8,%9}, {%0,%1,%2,%3};"
        : "+f"(c[0]), "+f"(c[1]), "+f"(c[2]), "+f"(c[3])
        : "r"(a[0]), "r"(a[1]), "r"(a[2]), "r"(a[3]), "r"(b[0]), "r"(b[1]));
}

// ---------------- CSR build ----------------
__global__ void hist_kernel(const int* __restrict__ ei) {
    int e = blockIdx.x * 256 + threadIdx.x;
    if (e >= ETOT) return;
    int d = (e < EE) ? ei[EE + e] : (e - EE);
    atomicAdd(&g_deg[d], 1);
}

__global__ void scan1_kernel() {
    __shared__ int sh[256];
    int tid = threadIdx.x;
    int i = blockIdx.x * 256 + tid;
    int v = (i < NN) ? g_deg[i] : 0;
    sh[tid] = v;
    __syncthreads();
#pragma unroll
    for (int off = 1; off < 256; off <<= 1) {
        int t = (tid >= off) ? sh[tid - off] : 0;
        __syncthreads();
        sh[tid] += t;
        __syncthreads();
    }
    if (i < NN) g_off[i] = sh[tid] - v;       // exclusive (local)
    if (tid == 255) g_part[blockIdx.x] = sh[255];
}

__global__ void scan2_kernel() {
    __shared__ int sh[256];
    int tid = threadIdx.x;
    int v = (tid < NB_SCAN) ? g_part[tid] : 0;
    sh[tid] = v;
    __syncthreads();
#pragma unroll
    for (int off = 1; off < 256; off <<= 1) {
        int t = (tid >= off) ? sh[tid - off] : 0;
        __syncthreads();
        sh[tid] += t;
        __syncthreads();
    }
    if (tid < NB_SCAN) g_part[tid] = sh[tid] - v;  // exclusive
}

__global__ void scan3_kernel() {
    int i = blockIdx.x * 256 + threadIdx.x;
    if (i < NN) {
        int o = g_off[i] + g_part[blockIdx.x];
        g_off[i] = o;
        g_cursor[i] = o;
    }
}

__global__ void scatter_kernel(const int* __restrict__ ei) {
    int e = blockIdx.x * 256 + threadIdx.x;
    if (e >= ETOT) return;
    int s, d;
    if (e < EE) { s = ei[e]; d = ei[EE + e]; }
    else        { s = e - EE; d = s; }
    int pos = atomicAdd(&g_cursor[d], 1);
    g_srcs[pos] = s;
}

// ---------------- av prep: g_avs[k*4+h] = sum_c W0[k][h*64+c] * a_src0[h][c] ----------------
__global__ void avprep_kernel(const float* __restrict__ W0,
                              const float* __restrict__ a_src0,
                              const float* __restrict__ a_dst0)
{
    int tid = threadIdx.x;            // 256 = 64 k x 4 h
    int k = tid >> 2;
    int h = tid & 3;
    float as = 0.f, ad = 0.f;
#pragma unroll 8
    for (int c = 0; c < HH; c++) {
        float w = W0[k * DD + h * HH + c];
        as += w * a_src0[h * HH + c];
        ad += w * a_dst0[h * HH + c];
    }
    g_avs[tid] = as;
    g_avd[tid] = ad;
}

// ---------------- esed0: es/ed per (t,n) from h0 (64-dim), warp per row ----------------
__global__ void __launch_bounds__(256) esed0_kernel()
{
    int gw = (blockIdx.x * 256 + threadIdx.x) >> 5;
    int lane = threadIdx.x & 31;
    if (gw >= TT * NN) return;
    float2 u = *(const float2*)(g_h0 + (size_t)gw * HH + lane * 2);
    float4 s0 = *(const float4*)(g_avs + lane * 8);
    float4 s1 = *(const float4*)(g_avs + lane * 8 + 4);
    float4 d0 = *(const float4*)(g_avd + lane * 8);
    float4 d1 = *(const float4*)(g_avd + lane * 8 + 4);
    float4 es, ed;
    es.x = u.x * s0.x + u.y * s1.x;  es.y = u.x * s0.y + u.y * s1.y;
    es.z = u.x * s0.z + u.y * s1.z;  es.w = u.x * s0.w + u.y * s1.w;
    ed.x = u.x * d0.x + u.y * d1.x;  ed.y = u.x * d0.y + u.y * d1.y;
    ed.z = u.x * d0.z + u.y * d1.z;  ed.w = u.x * d0.w + u.y * d1.w;
#pragma unroll
    for (int off = 16; off > 0; off >>= 1) {
        es.x += __shfl_xor_sync(0xffffffffu, es.x, off);
        es.y += __shfl_xor_sync(0xffffffffu, es.y, off);
        es.z += __shfl_xor_sync(0xffffffffu, es.z, off);
        es.w += __shfl_xor_sync(0xffffffffu, es.w, off);
        ed.x += __shfl_xor_sync(0xffffffffu, ed.x, off);
        ed.y += __shfl_xor_sync(0xffffffffu, ed.y, off);
        ed.z += __shfl_xor_sync(0xffffffffu, ed.z, off);
        ed.w += __shfl_xor_sync(0xffffffffu, ed.w, off);
    }
    if (lane == 0) {
        *(float4*)(g_esed + (size_t)gw * HEADS) = es;
        *(float4*)(g_esed + ESZ + (size_t)gw * HEADS) = ed;
    }
}

// ---------------- agg64: layer-0 aggregation in h0 space, warp per (t,dst) ----------------
// g_hp[gw][h*64+k] = (sum_e w_{e,h} * h0[src_e][k]) / (z_h + 1e-16)
__global__ void __launch_bounds__(256) agg64_kernel()
{
    int gw = (blockIdx.x * 256 + threadIdx.x) >> 5;
    int lane = threadIdx.x & 31;
    if (gw >= TT * NN) return;
    int t = gw / NN;
    int d = gw - t * NN;
    int base = g_off[d];
    int deg = g_deg[d];
    const size_t tN = (size_t)t * NN;
    float4 ed4 = *(const float4*)(g_esed + ESZ + (size_t)gw * HEADS);

    float4 z = make_float4(0.f, 0.f, 0.f, 0.f);
    float2 a0 = make_float2(0.f, 0.f), a1 = a0, a2 = a0, a3 = a0;
    for (int j = 0; j < deg; j++) {
        int s = g_srcs[base + j];
        float4 es4 = *(const float4*)(g_esed + (tN + s) * HEADS);
        float v, w0, w1, w2, w3;
        v = es4.x + ed4.x; v = v > 0.f ? v : NEG_SLOPE * v; w0 = expf(v);
        v = es4.y + ed4.y; v = v > 0.f ? v : NEG_SLOPE * v; w1 = expf(v);
        v = es4.z + ed4.z; v = v > 0.f ? v : NEG_SLOPE * v; w2 = expf(v);
        v = es4.w + ed4.w; v = v > 0.f ? v : NEG_SLOPE * v; w3 = expf(v);
        z.x += w0; z.y += w1; z.z += w2; z.w += w3;
        float2 u = *(const float2*)(g_h0 + (tN + s) * HH + lane * 2);
        a0.x += w0 * u.x; a0.y += w0 * u.y;
        a1.x += w1 * u.x; a1.y += w1 * u.y;
        a2.x += w2 * u.x; a2.y += w2 * u.y;
        a3.x += w3 * u.x; a3.y += w3 * u.y;
    }
    float i0 = 1.f / (z.x + 1e-16f), i1 = 1.f / (z.y + 1e-16f);
    float i2 = 1.f / (z.z + 1e-16f), i3 = 1.f / (z.w + 1e-16f);
    float* out = g_hp + (size_t)gw * DD;
    ((float2*)(out      ))[lane] = make_float2(a0.x * i0, a0.y * i0);
    ((float2*)(out +  64))[lane] = make_float2(a1.x * i1, a1.y * i1);
    ((float2*)(out + 128))[lane] = make_float2(a2.x * i2, a2.y * i2);
    ((float2*)(out + 192))[lane] = make_float2(a3.x * i3, a3.y * i3);
}

// ---------------- proj: bufA[:, c] = ELU( agg0[:, head(c) slice] @ W0[:, c] + b0[c] ) ----------------
// head-paired: block covers cols [128*bx, 128*bx+128) = heads 2bx, 2bx+1.
// Warp wn<2 uses left A slice (cols 128bx..+64), wn>=2 uses right (+64..+128). K=64.
__global__ void __launch_bounds__(256) proj_gemm(
    const float* __restrict__ A, const float* __restrict__ B,
    const float* __restrict__ bias, float* __restrict__ C, int Rows)
{
    __shared__ float AsL[16][136];
    __shared__ float AsR[16][136];
    __shared__ float Bs[16][136];
    const int tid = threadIdx.x;
    const int wid = tid >> 5;
    const int lane = tid & 31;
    const int wm = wid >> 2;
    const int wn = wid & 3;
    const int g = lane >> 2;
    const int t4 = lane & 3;
    const int rowBase = blockIdx.y << 7;
    const int colBase = blockIdx.x << 7;

    const int arow = tid >> 1;
    const int ak = (tid & 1) << 3;
    const int bk = wid;
    const int bcol = lane << 2;

    float acc[4][4][4];
#pragma unroll
    for (int mi = 0; mi < 4; mi++)
#pragma unroll
        for (int ni = 0; ni < 4; ni++)
#pragma unroll
            for (int q = 0; q < 4; q++) acc[mi][ni][q] = 0.f;

    const int gr = rowBase + arow;
    const bool aOK = gr < Rows;
    const float* Ap = A + (size_t)(aOK ? gr : 0) * DD + colBase + ak;
    const float* Bp = B + (size_t)bk * DD + colBase + bcol;

    for (int kt = 0; kt < 4; kt++) {
        const int kbase = kt << 4;
#pragma unroll
        for (int i = 0; i < 2; i++) {
            float4 vL = make_float4(0.f, 0.f, 0.f, 0.f);
            float4 vR = vL;
            if (aOK) {
                vL = *(const float4*)(Ap + kbase + i * 4);
                vR = *(const float4*)(Ap + 64 + kbase + i * 4);
            }
            int kb = ak + i * 4;
            AsL[kb + 0][arow] = __uint_as_float(f2tf32(vL.x));
            AsL[kb + 1][arow] = __uint_as_float(f2tf32(vL.y));
            AsL[kb + 2][arow] = __uint_as_float(f2tf32(vL.z));
            AsL[kb + 3][arow] = __uint_as_float(f2tf32(vL.w));
            AsR[kb + 0][arow] = __uint_as_float(f2tf32(vR.x));
            AsR[kb + 1][arow] = __uint_as_float(f2tf32(vR.y));
            AsR[kb + 2][arow] = __uint_as_float(f2tf32(vR.z));
            AsR[kb + 3][arow] = __uint_as_float(f2tf32(vR.w));
            float4 w = *(const float4*)(Bp + (size_t)(kbase + i * 8) * DD);
            float4 tw;
            tw.x = __uint_as_float(f2tf32(w.x));
            tw.y = __uint_as_float(f2tf32(w.y));
            tw.z = __uint_as_float(f2tf32(w.z));
            tw.w = __uint_as_float(f2tf32(w.w));
            *(float4*)&Bs[bk + i * 8][bcol] = tw;
        }
        __syncthreads();
        const float (*AsW)[136] = (wn < 2) ? AsL : AsR;
#pragma unroll
        for (int ks = 0; ks < 2; ks++) {
            const int k0 = ks * 8;
            uint32_t afr[4][4];
            uint32_t bfr[4][2];
#pragma unroll
            for (int mi = 0; mi < 4; mi++) {
                int row = (wm << 6) + (mi << 4) + g;
                afr[mi][0] = __float_as_uint(AsW[k0 + t4][row]);
                afr[mi][1] = __float_as_uint(AsW[k0 + t4][row + 8]);
                afr[mi][2] = __float_as_uint(AsW[k0 + t4 + 4][row]);
                afr[mi][3] = __float_as_uint(AsW[k0 + t4 + 4][row + 8]);
            }
#pragma unroll
            for (int ni = 0; ni < 4; ni++) {
                int col = (wn << 5) + (ni << 3) + g;
                bfr[ni][0] = __float_as_uint(Bs[k0 + t4][col]);
                bfr[ni][1] = __float_as_uint(Bs[k0 + t4 + 4][col]);
            }
#pragma unroll
            for (int mi = 0; mi < 4; mi++)
#pragma unroll
                for (int ni = 0; ni < 4; ni++)
                    mma_tf32(acc[mi][ni], afr[mi], bfr[ni]);
        }
        __syncthreads();
    }

    // epilogue: bias + ELU
#pragma unroll
    for (int mi = 0; mi < 4; mi++) {
        int row0 = rowBase + (wm << 6) + (mi << 4) + g;
        int row1 = row0 + 8;
#pragma unroll
        for (int ni = 0; ni < 4; ni++) {
            int col = colBase + (wn << 5) + (ni << 3) + (t4 << 1);
            float bx = bias[col], by = bias[col + 1];
            if (row0 < Rows) {
                float* cp = C + (size_t)row0 * DD + col;
                cp[0] = eluf(acc[mi][ni][0] + bx);
                cp[1] = eluf(acc[mi][ni][1] + by);
            }
            if (row1 < Rows) {
                float* cp = C + (size_t)row1 * DD + col;
                cp[0] = eluf(acc[mi][ni][2] + bx);
                cp[1] = eluf(acc[mi][ni][3] + by);
            }
        }
    }
}

// ---------------- tf32 tensor-core GEMM, double-buffered, fused esed / blend ----------------
template<int BLEND>
__global__ void __launch_bounds__(256) gemm_tf32(
    const float* __restrict__ A, const float* __restrict__ B,
    const float* __restrict__ bias, float* __restrict__ C,
    int Rows, int K, int Ncols, int permT, int permN,
    const float* __restrict__ asrc, const float* __restrict__ adst)
{
    __shared__ float As[2][16][136];
    __shared__ float Bs[2][16][136];
    const int tid = threadIdx.x;
    const int wid = tid >> 5;
    const int lane = tid & 31;
    const int wm = wid >> 2;
    const int wn = wid & 3;
    const int g = lane >> 2;
    const int t4 = lane & 3;
    const int rowBase = blockIdx.y << 7;
    const int colBase = blockIdx.x << 7;

    const int arow = tid >> 1;
    const int ak = (tid & 1) << 3;
    const int bk = wid;
    const int bcol = lane << 2;

    float acc[4][4][4];
#pragma unroll
    for (int mi = 0; mi < 4; mi++)
#pragma unroll
        for (int ni = 0; ni < 4; ni++)
#pragma unroll
            for (int q = 0; q < 4; q++) acc[mi][ni][q] = 0.f;

    const int gr = rowBase + arow;
    const bool aOK = gr < Rows;
    const float* Ap = A + (size_t)(aOK ? gr : 0) * K + ak;
    const bool bOK = (colBase + bcol) < Ncols;
    const float* Bp = B + (size_t)bk * Ncols + colBase + bcol;
    const size_t SLAB = (size_t)NN * DD;

    float atw0 = 0.f, atw1 = 0.f, atw2 = 0.f, atw3 = 0.f;
    if (BLEND) { atw0 = g_attn[0]; atw1 = g_attn[1]; atw2 = g_attn[2]; atw3 = g_attn[3]; }

    const int nk = K >> 4;
    float4 ra[2], rb[2];

    auto load_tile = [&](int kt) {
        const int kbase = kt << 4;
#pragma unroll
        for (int i = 0; i < 2; i++) {
            float4 v = make_float4(0.f, 0.f, 0.f, 0.f);
            if (aOK) {
                const float* p = Ap + kbase + i * 4;
                if (BLEND) {
                    float4 u0 = *(const float4*)(p);
                    float4 u1 = *(const float4*)(p + SLAB);
                    float4 u2 = *(const float4*)(p + 2 * SLAB);
                    float4 u3 = *(const float4*)(p + 3 * SLAB);
                    v.x = atw0 * u0.x + atw1 * u1.x + atw2 * u2.x + atw3 * u3.x;
                    v.y = atw0 * u0.y + atw1 * u1.y + atw2 * u2.y + atw3 * u3.y;
                    v.z = atw0 * u0.z + atw1 * u1.z + atw2 * u2.z + atw3 * u3.z;
                    v.w = atw0 * u0.w + atw1 * u1.w + atw2 * u2.w + atw3 * u3.w;
                } else {
                    v = *(const float4*)p;
                }
            }
            ra[i] = v;
            float4 w = make_float4(0.f, 0.f, 0.f, 0.f);
            if (bOK) w = *(const float4*)(Bp + (size_t)(kbase + i * 8) * Ncols);
            rb[i] = w;
        }
    };
    auto store_tile = [&](int buf) {
#pragma unroll
        for (int i = 0; i < 2; i++) {
            int kb = ak + i * 4;
            As[buf][kb + 0][arow] = __uint_as_float(f2tf32(ra[i].x));
            As[buf][kb + 1][arow] = __uint_as_float(f2tf32(ra[i].y));
            As[buf][kb + 2][arow] = __uint_as_float(f2tf32(ra[i].z));
            As[buf][kb + 3][arow] = __uint_as_float(f2tf32(ra[i].w));
            float4 w;
            w.x = __uint_as_float(f2tf32(rb[i].x));
            w.y = __uint_as_float(f2tf32(rb[i].y));
            w.z = __uint_as_float(f2tf32(rb[i].z));
            w.w = __uint_as_float(f2tf32(rb[i].w));
            *(float4*)&Bs[buf][bk + i * 8][bcol] = w;
        }
    };

    load_tile(0);
    store_tile(0);
    __syncthreads();

    for (int kt = 0; kt < nk; kt++) {
        const int buf = kt & 1;
        if (kt + 1 < nk) load_tile(kt + 1);
#pragma unroll
        for (int ks = 0; ks < 2; ks++) {
            const int k0 = ks * 8;
            uint32_t afr[4][4];
            uint32_t bfr[4][2];
#pragma unroll
            for (int mi = 0; mi < 4; mi++) {
                int row = (wm << 6) + (mi << 4) + g;
                afr[mi][0] = __float_as_uint(As[buf][k0 + t4][row]);
                afr[mi][1] = __float_as_uint(As[buf][k0 + t4][row + 8]);
                afr[mi][2] = __float_as_uint(As[buf][k0 + t4 + 4][row]);
                afr[mi][3] = __float_as_uint(As[buf][k0 + t4 + 4][row + 8]);
            }
#pragma unroll
            for (int ni = 0; ni < 4; ni++) {
                int col = (wn << 5) + (ni << 3) + g;
                bfr[ni][0] = __float_as_uint(Bs[buf][k0 + t4][col]);
                bfr[ni][1] = __float_as_uint(Bs[buf][k0 + t4 + 4][col]);
            }
#pragma unroll
            for (int mi = 0; mi < 4; mi++)
#pragma unroll
                for (int ni = 0; ni < 4; ni++)
                    mma_tf32(acc[mi][ni], afr[mi], bfr[ni]);
        }
        if (kt + 1 < nk) {
            store_tile(buf ^ 1);
            __syncthreads();
        }
    }

    // ---- epilogue ----
#pragma unroll
    for (int mi = 0; mi < 4; mi++) {
        int row0 = rowBase + (wm << 6) + (mi << 4) + g;
        int row1 = row0 + 8;
        int orow0 = -1, orow1 = -1;
        if (row0 < Rows) orow0 = permT ? ((row0 % permT) * permN + row0 / permT) : row0;
        if (row1 < Rows) orow1 = permT ? ((row1 % permT) * permN + row1 / permT) : row1;
        float es0 = 0.f, es1 = 0.f, ed0 = 0.f, ed1 = 0.f;
#pragma unroll
        for (int ni = 0; ni < 4; ni++) {
            int col = colBase + (wn << 5) + (ni << 3) + (t4 << 1);
            if (col < Ncols) {
                float bx = 0.f, by = 0.f;
                if (bias) { bx = bias[col]; by = bias[col + 1]; }
                float c00 = acc[mi][ni][0] + bx;
                float c01 = acc[mi][ni][1] + by;
                float c10 = acc[mi][ni][2] + bx;
                float c11 = acc[mi][ni][3] + by;
                if (orow0 >= 0) {
                    float* cp = C + (size_t)orow0 * Ncols + col;
                    cp[0] = c00;
                    cp[1] = c01;
                }
                if (orow1 >= 0) {
                    float* cp = C + (size_t)orow1 * Ncols + col;
                    cp[0] = c10;
                    cp[1] = c11;
                }
                if (asrc) {
                    float sx = __ldg(asrc + col), sy = __ldg(asrc + col + 1);
                    float dx = __ldg(adst + col), dy = __ldg(adst + col + 1);
                    es0 += c00 * sx + c01 * sy;
                    ed0 += c00 * dx + c01 * dy;
                    es1 += c10 * sx + c11 * sy;
                    ed1 += c10 * dx + c11 * dy;
                }
            }
        }
        if (asrc) {
            es0 += __shfl_xor_sync(0xffffffffu, es0, 1);
            es0 += __shfl_xor_sync(0xffffffffu, es0, 2);
            es1 += __shfl_xor_sync(0xffffffffu, es1, 1);
            es1 += __shfl_xor_sync(0xffffffffu, es1, 2);
            ed0 += __shfl_xor_sync(0xffffffffu, ed0, 1);
            ed0 += __shfl_xor_sync(0xffffffffu, ed0, 2);
            ed1 += __shfl_xor_sync(0xffffffffu, ed1, 1);
            ed1 += __shfl_xor_sync(0xffffffffu, ed1, 2);
            if (t4 == 0) {
                int head = (colBase + (wn << 5)) >> 6;
                if (orow0 >= 0) {
                    atomicAdd(&g_esed[(size_t)orow0 * HEADS + head], es0);
                    atomicAdd(&g_esed[ESZ + (size_t)orow0 * HEADS + head], ed0);
                }
                if (orow1 >= 0) {
                    atomicAdd(&g_esed[(size_t)orow1 * HEADS + head], es1);
                    atomicAdd(&g_esed[ESZ + (size_t)orow1 * HEADS + head], ed1);
                }
            }
        }
    }
}

// ---------------- layer-1 fused softmax + aggregation (256-dim gather) ----------------
__global__ void __launch_bounds__(256) agg_kernel(const float* __restrict__ bias,
                                                  float* __restrict__ out)
{
    int gw = (blockIdx.x * 256 + threadIdx.x) >> 5;
    int lane = threadIdx.x & 31;
    if (gw >= TT * NN) return;
    int t = gw / NN;
    int d = gw - t * NN;
    int base = g_off[d];
    int deg = g_deg[d];
    const size_t tN = (size_t)t * NN;
    int myh = lane >> 3;
    float edh = __ldg(g_esed + ESZ + (size_t)gw * HEADS + myh);

    float z = 0.f;
    float4 a0 = make_float4(0.f, 0.f, 0.f, 0.f);
    float4 a1 = make_float4(0.f, 0.f, 0.f, 0.f);
    for (int j = 0; j < deg; j++) {
        int s = g_srcs[base + j];
        float es = __ldg(g_esed + (tN + s) * HEADS + myh);
        float v = es + edh;
        v = v > 0.f ? v : NEG_SLOPE * v;
        float w = expf(v);
        z += w;
        const float4* r = (const float4*)(g_hp + (tN + s) * DD) + lane * 2;
        float4 u0 = __ldg(r);
        float4 u1 = __ldg(r + 1);
        a0.x += w * u0.x; a0.y += w * u0.y;
        a0.z += w * u0.z; a0.w += w * u0.w;
        a1.x += w * u1.x; a1.y += w * u1.y;
        a1.z += w * u1.z; a1.w += w * u1.w;
    }
    float zinv = 1.f / (z + 1e-16f);

    const float4* bp4 = (const float4*)bias + lane * 2;
    float4 b0v = __ldg(bp4), b1v = __ldg(bp4 + 1);
    float4 o0, o1;
    o0.x = eluf(a0.x * zinv + b0v.x); o0.y = eluf(a0.y * zinv + b0v.y);
    o0.z = eluf(a0.z * zinv + b0v.z); o0.w = eluf(a0.w * zinv + b0v.w);
    o1.x = eluf(a1.x * zinv + b1v.x); o1.y = eluf(a1.y * zinv + b1v.y);
    o1.z = eluf(a1.z * zinv + b1v.z); o1.w = eluf(a1.w * zinv + b1v.w);
    float4* op = (float4*)(out + (size_t)gw * DD) + lane * 2;
    op[0] = o0;
    op[1] = o1;
}

// ---------------- per-t column sums of embs (bufB) ----------------
__global__ void __launch_bounds__(256) colsum_kernel()
{
    int t = blockIdx.y;
    int c = threadIdx.x;
    float s = 0.f;
    for (int n = blockIdx.x; n < NN; n += gridDim.x)
        s += g_bufB[((size_t)t * NN + n) * DD + c];
    atomicAdd(&g_colsum[t * DD + c], s);
}

// ---------------- temporal attention weights (single block) ----------------
__global__ void __launch_bounds__(256) attn_kernel(
    const float* __restrict__ Wq, const float* __restrict__ bq,
    const float* __restrict__ Wk, const float* __restrict__ bk)
{
    __shared__ float mean[TT][DD];
    __shared__ float Kt[TT][DD];
    __shared__ float Qv[DD];
    __shared__ float red[256];
    __shared__ float sc[TT];
    int c = threadIdx.x;
#pragma unroll
    for (int t = 0; t < TT; t++)
        mean[t][c] = g_colsum[t * DD + c] * (1.0f / (float)NN);
    __syncthreads();
#pragma unroll
    for (int t = 0; t < TT; t++) {
        float acc = bk[c];
        for (int f = 0; f < DD; f++) acc += mean[t][f] * Wk[f * DD + c];
        Kt[t][c] = acc;
    }
    {
        float acc = bq[c];
        for (int f = 0; f < DD; f++) acc += mean[TT - 1][f] * Wq[f * DD + c];
        Qv[c] = acc;
    }
    __syncthreads();
    for (int t = 0; t < TT; t++) {
        red[c] = Qv[c] * Kt[t][c];
        __syncthreads();
        for (int off = 128; off > 0; off >>= 1) {
            if (c < off) red[c] += red[c + off];
            __syncthreads();
        }
        if (c == 0) sc[t] = red[0] * (1.0f / 16.0f);   // 1/sqrt(256)
        __syncthreads();
    }
    if (c == 0) {
        float m = fmaxf(fmaxf(sc[0], sc[1]), fmaxf(sc[2], sc[3]));
        float w0 = expf(sc[0] - m), w1 = expf(sc[1] - m);
        float w2 = expf(sc[2] - m), w3 = expf(sc[3] - m);
        float inv = 1.0f / (w0 + w1 + w2 + w3);
        g_attn[0] = w0 * inv; g_attn[1] = w1 * inv;
        g_attn[2] = w2 * inv; g_attn[3] = w3 * inv;
    }
}

// ---------------- launch ----------------
extern "C" void kernel_launch(void* const* d_in, const int* in_sizes, int n_in,
                              void* d_out, int out_size)
{
    const float* x      = (const float*)d_in[0];
    const int*   ei     = (const int*)  d_in[1];
    const float* Wp     = (const float*)d_in[2];
    const float* bp     = (const float*)d_in[3];
    const float* W0     = (const float*)d_in[4];
    const float* a_src0 = (const float*)d_in[5];
    const float* a_dst0 = (const float*)d_in[6];
    const float* b0     = (const float*)d_in[7];
    const float* W1     = (const float*)d_in[8];
    const float* a_src1 = (const float*)d_in[9];
    const float* a_dst1 = (const float*)d_in[10];
    const float* b1     = (const float*)d_in[11];
    const float* Wq     = (const float*)d_in[12];
    const float* bq     = (const float*)d_in[13];
    const float* Wk     = (const float*)d_in[14];
    const float* bk     = (const float*)d_in[15];
    const float* Wv     = (const float*)d_in[16];
    const float* bv     = (const float*)d_in[17];

    float *h0, *hp, *bufA, *bufB, *esed, *cs;
    int *degp;
    cudaGetSymbolAddress((void**)&h0,   g_h0);
    cudaGetSymbolAddress((void**)&hp,   g_hp);
    cudaGetSymbolAddress((void**)&bufA, g_bufA);
    cudaGetSymbolAddress((void**)&bufB, g_bufB);
    cudaGetSymbolAddress((void**)&esed, g_esed);
    cudaGetSymbolAddress((void**)&cs,   g_colsum);
    cudaGetSymbolAddress((void**)&degp, g_deg);

    const int rowsTN = TT * NN;            // 120000
    const int edges  = ETOT;               // 270000
    const int gy = (rowsTN + 127) / 128;   // 938
    const int esed4 = 2 * ESZ / 4;         // 480000

    // ---- CSR build (graph shared across t and both layers) ----
    zero_kernel<<<(NN / 4 + 255) / 256, 256>>>((float4*)degp, NN / 4);
    hist_kernel<<<(edges + 255) / 256, 256>>>(ei);
    scan1_kernel<<<NB_SCAN, 256>>>();
    scan2_kernel<<<1, 256>>>();
    scan3_kernel<<<NB_SCAN, 256>>>();
    scatter_kernel<<<(edges + 255) / 256, 256>>>(ei);

    // ---- av vectors for layer-0 logits ----
    avprep_kernel<<<1, 256>>>(W0, a_src0, a_dst0);

    // ---- h0(t,n) = x[n,t] @ Wp + bp  (bias folded, perm output) ----
    gemm_tf32<0><<<dim3(1, gy), 256>>>(x, Wp, bp, h0, rowsTN, FIN, HH,
                                       TT, NN, nullptr, nullptr);

    // ---- GAT layer 0: logits from h0, aggregate in h0 space, project + b0 + ELU ----
    esed0_kernel<<<(rowsTN + 7) / 8, 256>>>();
    agg64_kernel<<<(rowsTN + 7) / 8, 256>>>();          // -> g_hp (agg0)
    proj_gemm<<<dim3(2, gy), 256>>>(hp, W0, b0, bufA, rowsTN);

    // ---- GAT layer 1 ----
    zero_kernel<<<(esed4 + 255) / 256, 256>>>((float4*)esed, esed4);
    gemm_tf32<0><<<dim3(2, gy), 256>>>(bufA, W1, nullptr, hp, rowsTN, DD, DD,
                                       0, 0, a_src1, a_dst1);
    agg_kernel<<<(rowsTN + 7) / 8, 256>>>(b1, bufB);

    // ---- temporal attention ----
    zero_kernel<<<1, 256>>>((float4*)cs, TT * DD / 4);
    colsum_kernel<<<dim3(128, TT), 256>>>();
    attn_kernel<<<1, 256>>>(Wq, bq, Wk, bk);

    // ---- out = (sum_t attn[t] * embs_t) @ Wv + bv  (blend fused into A-load) ----
    gemm_tf32<1><<<dim3(2, (NN + 127) / 128), 256>>>(bufB, Wv, bv, (float*)d_out,
                                                     NN, DD, DD, 0, 0, nullptr, nullptr);
}

// round 12
// speedup vs baseline: 1.0684x; 1.0684x over previous
#include <cuda_runtime.h>
#include <math.h>
#include <stdint.h>

#define NN 30000
#define TT 4
#define FIN 256
#define HH 64
#define HEADS 4
#define DD 256
#define EE 240000
#define ETOT 270000            // EE + NN self loops
#define NEG_SLOPE 0.2f
#define NB_SCAN 118            // ceil(NN/256)
#define ESZ (TT * NN * HEADS)

// ---------------- scratch (device globals: allocation-free) ----------------
__device__ __align__(16) float g_h0[TT * NN * HH];     // xWp output (incl bp), (t,n) order
__device__ __align__(16) float g_hp[TT * NN * DD];     // per-layer hp = h @ W
__device__ __align__(16) float g_bufA[TT * NN * DD];   // layer0 output (post ELU)
__device__ __align__(16) float g_bufB[TT * NN * DD];   // layer1 output (embs)
__device__ __align__(16) float g_esed[2 * ESZ];        // es at 0, ed at ESZ
__device__ __align__(16) float g_colsum[TT * DD];
__device__ float g_attn[TT];
// CSR
__device__ int g_deg[NN];
__device__ int g_off[NN];
__device__ int g_cursor[NN];
__device__ int g_part[256];
__device__ int g_srcs[ETOT];

// ---------------- utility ----------------
__global__ void zero_kernel(float4* __restrict__ p, int n4) {
    int i = blockIdx.x * blockDim.x + threadIdx.x;
    if (i < n4) p[i] = make_float4(0.f, 0.f, 0.f, 0.f);
}

__device__ __forceinline__ float eluf(float x) { return x > 0.f ? x : expm1f(x); }

// RNA rounding to tf32 is load-bearing: truncation biases the K-sum coherently
// and quadruples rel_err (measured R10). Do not remove.
__device__ __forceinline__ uint32_t f2tf32(float x) {
    uint32_t r;
    asm("cvt.rna.tf32.f32 %0, %1;" : "=r"(r) : "f"(x));
    return r;
}

__device__ __forceinline__ void mma_tf32(float* c, const uint32_t* a, const uint32_t* b) {
    asm volatile(
        "mma.sync.aligned.m16n8k8.row.col.f32.tf32.tf32.f32 "
        "{%0,%1,%2,%3}, {%4,%5,%6,%7}, {%8,%9}, {%0,%1,%2,%3};"
        : "+f"(c[0]), "+f"(c[1]), "+f"(c[2]), "+f"(c[3])
        : "r"(a[0]), "r"(a[1]), "r"(a[2]), "r"(a[3]), "r"(b[0]), "r"(b[1]));
}

// ---------------- CSR build ----------------
__global__ void hist_kernel(const int* __restrict__ ei) {
    int e = blockIdx.x * 256 + threadIdx.x;
    if (e >= ETOT) return;
    int d = (e < EE) ? ei[EE + e] : (e - EE);
    atomicAdd(&g_deg[d], 1);
}

__global__ void scan1_kernel() {
    __shared__ int sh[256];
    int tid = threadIdx.x;
    int i = blockIdx.x * 256 + tid;
    int v = (i < NN) ? g_deg[i] : 0;
    sh[tid] = v;
    __syncthreads();
#pragma unroll
    for (int off = 1; off < 256; off <<= 1) {
        int t = (tid >= off) ? sh[tid - off] : 0;
        __syncthreads();
        sh[tid] += t;
        __syncthreads();
    }
    if (i < NN) g_off[i] = sh[tid] - v;       // exclusive (local)
    if (tid == 255) g_part[blockIdx.x] = sh[255];
}

__global__ void scan2_kernel() {
    __shared__ int sh[256];
    int tid = threadIdx.x;
    int v = (tid < NB_SCAN) ? g_part[tid] : 0;
    sh[tid] = v;
    __syncthreads();
#pragma unroll
    for (int off = 1; off < 256; off <<= 1) {
        int t = (tid >= off) ? sh[tid - off] : 0;
        __syncthreads();
        sh[tid] += t;
        __syncthreads();
    }
    if (tid < NB_SCAN) g_part[tid] = sh[tid] - v;  // exclusive
}

__global__ void scan3_kernel() {
    int i = blockIdx.x * 256 + threadIdx.x;
    if (i < NN) {
        int o = g_off[i] + g_part[blockIdx.x];
        g_off[i] = o;
        g_cursor[i] = o;
    }
}

__global__ void scatter_kernel(const int* __restrict__ ei) {
    int e = blockIdx.x * 256 + threadIdx.x;
    if (e >= ETOT) return;
    int s, d;
    if (e < EE) { s = ei[e]; d = ei[EE + e]; }
    else        { s = e - EE; d = s; }
    int pos = atomicAdd(&g_cursor[d], 1);
    g_srcs[pos] = s;
}

// ---------------- tf32 tensor-core GEMM, double-buffered, fused esed / blend ----------------
// C(R x Nc) = A(R x K) @ B(K x Nc) (+bias). 128x128 tile, KTILE=16, 256 threads.
// permT!=0: output row r=(n*permT+t) -> t*permN+n.
// asrc/adst != null: accumulate per-head dots of the BIASED output row into g_esed
//                    (g_esed must be pre-zeroed).
// BLEND: A row r = sum_t g_attn[t] * A[t*SLAB + r*K + k] (A = bufB base).
template<int BLEND>
__global__ void __launch_bounds__(256) gemm_tf32(
    const float* __restrict__ A, const float* __restrict__ B,
    const float* __restrict__ bias, float* __restrict__ C,
    int Rows, int K, int Ncols, int permT, int permN,
    const float* __restrict__ asrc, const float* __restrict__ adst)
{
    __shared__ float As[2][16][136];   // [k][row], pad -> frag bank = 8k+row (conflict-free)
    __shared__ float Bs[2][16][136];   // [k][col]
    const int tid = threadIdx.x;
    const int wid = tid >> 5;
    const int lane = tid & 31;
    const int wm = wid >> 2;        // 0..1
    const int wn = wid & 3;         // 0..3
    const int g = lane >> 2;        // 0..7
    const int t4 = lane & 3;        // 0..3
    const int rowBase = blockIdx.y << 7;
    const int colBase = blockIdx.x << 7;

    const int arow = tid >> 1;            // 0..127
    const int ak = (tid & 1) << 3;        // 0 / 8
    const int bk = wid;                   // rows bk, bk+8
    const int bcol = lane << 2;           // 0..124

    float acc[4][4][4];
#pragma unroll
    for (int mi = 0; mi < 4; mi++)
#pragma unroll
        for (int ni = 0; ni < 4; ni++)
#pragma unroll
            for (int q = 0; q < 4; q++) acc[mi][ni][q] = 0.f;

    const int gr = rowBase + arow;
    const bool aOK = gr < Rows;
    const float* Ap = A + (size_t)(aOK ? gr : 0) * K + ak;
    const bool bOK = (colBase + bcol) < Ncols;
    const float* Bp = B + (size_t)bk * Ncols + colBase + bcol;
    const size_t SLAB = (size_t)NN * DD;

    float atw0 = 0.f, atw1 = 0.f, atw2 = 0.f, atw3 = 0.f;
    if (BLEND) { atw0 = g_attn[0]; atw1 = g_attn[1]; atw2 = g_attn[2]; atw3 = g_attn[3]; }

    const int nk = K >> 4;
    float4 ra[2], rb[2];

    auto load_tile = [&](int kt) {
        const int kbase = kt << 4;
#pragma unroll
        for (int i = 0; i < 2; i++) {
            float4 v = make_float4(0.f, 0.f, 0.f, 0.f);
            if (aOK) {
                const float* p = Ap + kbase + i * 4;
                if (BLEND) {
                    float4 u0 = *(const float4*)(p);
                    float4 u1 = *(const float4*)(p + SLAB);
                    float4 u2 = *(const float4*)(p + 2 * SLAB);
                    float4 u3 = *(const float4*)(p + 3 * SLAB);
                    v.x = atw0 * u0.x + atw1 * u1.x + atw2 * u2.x + atw3 * u3.x;
                    v.y = atw0 * u0.y + atw1 * u1.y + atw2 * u2.y + atw3 * u3.y;
                    v.z = atw0 * u0.z + atw1 * u1.z + atw2 * u2.z + atw3 * u3.z;
                    v.w = atw0 * u0.w + atw1 * u1.w + atw2 * u2.w + atw3 * u3.w;
                } else {
                    v = *(const float4*)p;
                }
            }
            ra[i] = v;
            float4 w = make_float4(0.f, 0.f, 0.f, 0.f);
            if (bOK) w = *(const float4*)(Bp + (size_t)(kbase + i * 8) * Ncols);
            rb[i] = w;
        }
    };
    auto store_tile = [&](int buf) {
#pragma unroll
        for (int i = 0; i < 2; i++) {
            int kb = ak + i * 4;
            As[buf][kb + 0][arow] = __uint_as_float(f2tf32(ra[i].x));
            As[buf][kb + 1][arow] = __uint_as_float(f2tf32(ra[i].y));
            As[buf][kb + 2][arow] = __uint_as_float(f2tf32(ra[i].z));
            As[buf][kb + 3][arow] = __uint_as_float(f2tf32(ra[i].w));
            float4 w;
            w.x = __uint_as_float(f2tf32(rb[i].x));
            w.y = __uint_as_float(f2tf32(rb[i].y));
            w.z = __uint_as_float(f2tf32(rb[i].z));
            w.w = __uint_as_float(f2tf32(rb[i].w));
            *(float4*)&Bs[buf][bk + i * 8][bcol] = w;
        }
    };

    load_tile(0);
    store_tile(0);
    __syncthreads();

    for (int kt = 0; kt < nk; kt++) {
        const int buf = kt & 1;
        if (kt + 1 < nk) load_tile(kt + 1);
#pragma unroll
        for (int ks = 0; ks < 2; ks++) {
            const int k0 = ks * 8;
            uint32_t afr[4][4];
            uint32_t bfr[4][2];
#pragma unroll
            for (int mi = 0; mi < 4; mi++) {
                int row = (wm << 6) + (mi << 4) + g;
                afr[mi][0] = __float_as_uint(As[buf][k0 + t4][row]);
                afr[mi][1] = __float_as_uint(As[buf][k0 + t4][row + 8]);
                afr[mi][2] = __float_as_uint(As[buf][k0 + t4 + 4][row]);
                afr[mi][3] = __float_as_uint(As[buf][k0 + t4 + 4][row + 8]);
            }
#pragma unroll
            for (int ni = 0; ni < 4; ni++) {
                int col = (wn << 5) + (ni << 3) + g;
                bfr[ni][0] = __float_as_uint(Bs[buf][k0 + t4][col]);
                bfr[ni][1] = __float_as_uint(Bs[buf][k0 + t4 + 4][col]);
            }
#pragma unroll
            for (int mi = 0; mi < 4; mi++)
#pragma unroll
                for (int ni = 0; ni < 4; ni++)
                    mma_tf32(acc[mi][ni], afr[mi], bfr[ni]);
        }
        if (kt + 1 < nk) {
            store_tile(buf ^ 1);
            __syncthreads();
        }
    }

    // ---- epilogue: bias -> C value, store C, fused es/ed dots on biased values ----
#pragma unroll
    for (int mi = 0; mi < 4; mi++) {
        int row0 = rowBase + (wm << 6) + (mi << 4) + g;
        int row1 = row0 + 8;
        int orow0 = -1, orow1 = -1;
        if (row0 < Rows) orow0 = permT ? ((row0 % permT) * permN + row0 / permT) : row0;
        if (row1 < Rows) orow1 = permT ? ((row1 % permT) * permN + row1 / permT) : row1;
        float es0 = 0.f, es1 = 0.f, ed0 = 0.f, ed1 = 0.f;
#pragma unroll
        for (int ni = 0; ni < 4; ni++) {
            int col = colBase + (wn << 5) + (ni << 3) + (t4 << 1);
            if (col < Ncols) {
                float bx = 0.f, by = 0.f;
                if (bias) { bx = bias[col]; by = bias[col + 1]; }
                float c00 = acc[mi][ni][0] + bx;
                float c01 = acc[mi][ni][1] + by;
                float c10 = acc[mi][ni][2] + bx;
                float c11 = acc[mi][ni][3] + by;
                if (orow0 >= 0) {
                    float* cp = C + (size_t)orow0 * Ncols + col;
                    cp[0] = c00;
                    cp[1] = c01;
                }
                if (orow1 >= 0) {
                    float* cp = C + (size_t)orow1 * Ncols + col;
                    cp[0] = c10;
                    cp[1] = c11;
                }
                if (asrc) {
                    float sx = __ldg(asrc + col), sy = __ldg(asrc + col + 1);
                    float dx = __ldg(adst + col), dy = __ldg(adst + col + 1);
                    es0 += c00 * sx + c01 * sy;
                    ed0 += c00 * dx + c01 * dy;
                    es1 += c10 * sx + c11 * sy;
                    ed1 += c10 * dx + c11 * dy;
                }
            }
        }
        if (asrc) {
            es0 += __shfl_xor_sync(0xffffffffu, es0, 1);
            es0 += __shfl_xor_sync(0xffffffffu, es0, 2);
            es1 += __shfl_xor_sync(0xffffffffu, es1, 1);
            es1 += __shfl_xor_sync(0xffffffffu, es1, 2);
            ed0 += __shfl_xor_sync(0xffffffffu, ed0, 1);
            ed0 += __shfl_xor_sync(0xffffffffu, ed0, 2);
            ed1 += __shfl_xor_sync(0xffffffffu, ed1, 1);
            ed1 += __shfl_xor_sync(0xffffffffu, ed1, 2);
            if (t4 == 0) {
                int head = (colBase + (wn << 5)) >> 6;
                if (orow0 >= 0) {
                    atomicAdd(&g_esed[(size_t)orow0 * HEADS + head], es0);
                    atomicAdd(&g_esed[ESZ + (size_t)orow0 * HEADS + head], ed0);
                }
                if (orow1 >= 0) {
                    atomicAdd(&g_esed[(size_t)orow1 * HEADS + head], es1);
                    atomicAdd(&g_esed[ESZ + (size_t)orow1 * HEADS + head], ed1);
                }
            }
        }
    }
}

// ---------------- fused softmax + aggregation, SINGLE PASS: warp per (t, dst) ----------------
// out = ELU( (sum_e w_e * hp[src]) / (z + 1e-16) + bias ),  w_e = exp(leaky(es+ed)), z = sum w_e
__global__ void __launch_bounds__(256) agg_kernel(const float* __restrict__ bias,
                                                  float* __restrict__ out)
{
    int gw = (blockIdx.x * 256 + threadIdx.x) >> 5;
    int lane = threadIdx.x & 31;
    if (gw >= TT * NN) return;
    int t = gw / NN;
    int d = gw - t * NN;
    int base = g_off[d];
    int deg = g_deg[d];
    const size_t tN = (size_t)t * NN;
    int myh = lane >> 3;                   // head of my 8 output cols
    float edh = __ldg(g_esed + ESZ + (size_t)gw * HEADS + myh);

    float z = 0.f;
    float4 a0 = make_float4(0.f, 0.f, 0.f, 0.f);
    float4 a1 = make_float4(0.f, 0.f, 0.f, 0.f);
    for (int j = 0; j < deg; j++) {
        int s = g_srcs[base + j];
        float es = __ldg(g_esed + (tN + s) * HEADS + myh);
        float v = es + edh;
        v = v > 0.f ? v : NEG_SLOPE * v;
        float w = __expf(v);
        z += w;
        const float4* r = (const float4*)(g_hp + (tN + s) * DD) + lane * 2;
        float4 u0 = __ldg(r);
        float4 u1 = __ldg(r + 1);
        a0.x += w * u0.x; a0.y += w * u0.y;
        a0.z += w * u0.z; a0.w += w * u0.w;
        a1.x += w * u1.x; a1.y += w * u1.y;
        a1.z += w * u1.z; a1.w += w * u1.w;
    }
    float zinv = 1.f / (z + 1e-16f);

    // ---- epilogue: normalize + bias + ELU, single write ----
    const float4* bp4 = (const float4*)bias + lane * 2;
    float4 b0v = __ldg(bp4), b1v = __ldg(bp4 + 1);
    float4 o0, o1;
    o0.x = eluf(a0.x * zinv + b0v.x); o0.y = eluf(a0.y * zinv + b0v.y);
    o0.z = eluf(a0.z * zinv + b0v.z); o0.w = eluf(a0.w * zinv + b0v.w);
    o1.x = eluf(a1.x * zinv + b1v.x); o1.y = eluf(a1.y * zinv + b1v.y);
    o1.z = eluf(a1.z * zinv + b1v.z); o1.w = eluf(a1.w * zinv + b1v.w);
    float4* op = (float4*)(out + (size_t)gw * DD) + lane * 2;
    op[0] = o0;
    op[1] = o1;
}

// ---------------- per-t column sums of embs (bufB) ----------------
__global__ void __launch_bounds__(256) colsum_kernel()
{
    int t = blockIdx.y;
    int c = threadIdx.x;
    float s = 0.f;
    for (int n = blockIdx.x; n < NN; n += gridDim.x)
        s += g_bufB[((size_t)t * NN + n) * DD + c];
    atomicAdd(&g_colsum[t * DD + c], s);
}

// ---------------- temporal attention weights (single block) ----------------
__global__ void __launch_bounds__(256) attn_kernel(
    const float* __restrict__ Wq, const float* __restrict__ bq,
    const float* __restrict__ Wk, const float* __restrict__ bk)
{
    __shared__ float mean[TT][DD];
    __shared__ float Kt[TT][DD];
    __shared__ float Qv[DD];
    __shared__ float red[256];
    __shared__ float sc[TT];
    int c = threadIdx.x;
#pragma unroll
    for (int t = 0; t < TT; t++)
        mean[t][c] = g_colsum[t * DD + c] * (1.0f / (float)NN);
    __syncthreads();
#pragma unroll
    for (int t = 0; t < TT; t++) {
        float acc = bk[c];
        for (int f = 0; f < DD; f++) acc += mean[t][f] * Wk[f * DD + c];
        Kt[t][c] = acc;
    }
    {
        float acc = bq[c];
        for (int f = 0; f < DD; f++) acc += mean[TT - 1][f] * Wq[f * DD + c];
        Qv[c] = acc;
    }
    __syncthreads();
    for (int t = 0; t < TT; t++) {
        red[c] = Qv[c] * Kt[t][c];
        __syncthreads();
        for (int off = 128; off > 0; off >>= 1) {
            if (c < off) red[c] += red[c + off];
            __syncthreads();
        }
        if (c == 0) sc[t] = red[0] * (1.0f / 16.0f);   // 1/sqrt(256)
        __syncthreads();
    }
    if (c == 0) {
        float m = fmaxf(fmaxf(sc[0], sc[1]), fmaxf(sc[2], sc[3]));
        float w0 = expf(sc[0] - m), w1 = expf(sc[1] - m);
        float w2 = expf(sc[2] - m), w3 = expf(sc[3] - m);
        float inv = 1.0f / (w0 + w1 + w2 + w3);
        g_attn[0] = w0 * inv; g_attn[1] = w1 * inv;
        g_attn[2] = w2 * inv; g_attn[3] = w3 * inv;
    }
}

// ---------------- launch ----------------
extern "C" void kernel_launch(void* const* d_in, const int* in_sizes, int n_in,
                              void* d_out, int out_size)
{
    const float* x      = (const float*)d_in[0];
    const int*   ei     = (const int*)  d_in[1];
    const float* Wp     = (const float*)d_in[2];
    const float* bp     = (const float*)d_in[3];
    const float* W0     = (const float*)d_in[4];
    const float* a_src0 = (const float*)d_in[5];
    const float* a_dst0 = (const float*)d_in[6];
    const float* b0     = (const float*)d_in[7];
    const float* W1     = (const float*)d_in[8];
    const float* a_src1 = (const float*)d_in[9];
    const float* a_dst1 = (const float*)d_in[10];
    const float* b1     = (const float*)d_in[11];
    const float* Wq     = (const float*)d_in[12];
    const float* bq     = (const float*)d_in[13];
    const float* Wk     = (const float*)d_in[14];
    const float* bk     = (const float*)d_in[15];
    const float* Wv     = (const float*)d_in[16];
    const float* bv     = (const float*)d_in[17];

    float *h0, *hp, *bufA, *bufB, *esed, *cs;
    int *degp;
    cudaGetSymbolAddress((void**)&h0,   g_h0);
    cudaGetSymbolAddress((void**)&hp,   g_hp);
    cudaGetSymbolAddress((void**)&bufA, g_bufA);
    cudaGetSymbolAddress((void**)&bufB, g_bufB);
    cudaGetSymbolAddress((void**)&esed, g_esed);
    cudaGetSymbolAddress((void**)&cs,   g_colsum);
    cudaGetSymbolAddress((void**)&degp, g_deg);

    const int rowsTN = TT * NN;            // 120000
    const int edges  = ETOT;               // 270000
    const int gy = (rowsTN + 127) / 128;   // 938
    const int esed4 = 2 * ESZ / 4;         // 480000

    // ---- CSR build (graph shared across t and both layers) ----
    zero_kernel<<<(NN / 4 + 255) / 256, 256>>>((float4*)degp, NN / 4);
    hist_kernel<<<(edges + 255) / 256, 256>>>(ei);
    scan1_kernel<<<NB_SCAN, 256>>>();
    scan2_kernel<<<1, 256>>>();
    scan3_kernel<<<NB_SCAN, 256>>>();
    scatter_kernel<<<(edges + 255) / 256, 256>>>(ei);

    // ---- h0(t,n) = x[n,t] @ Wp + bp  (64-wide, bias folded here, perm output) ----
    gemm_tf32<0><<<dim3(1, gy), 256>>>(x, Wp, bp, h0, rowsTN, FIN, HH,
                                       TT, NN, nullptr, nullptr);

    // ---- GAT layer 0: hp = h0 @ W0 (K=64), es/ed fused on outputs ----
    zero_kernel<<<(esed4 + 255) / 256, 256>>>((float4*)esed, esed4);
    gemm_tf32<0><<<dim3(2, gy), 256>>>(h0, W0, nullptr, hp, rowsTN, HH, DD,
                                       0, 0, a_src0, a_dst0);
    agg_kernel<<<(rowsTN + 7) / 8, 256>>>(b0, bufA);

    // ---- GAT layer 1 ----
    zero_kernel<<<(esed4 + 255) / 256, 256>>>((float4*)esed, esed4);
    gemm_tf32<0><<<dim3(2, gy), 256>>>(bufA, W1, nullptr, hp, rowsTN, DD, DD,
                                       0, 0, a_src1, a_dst1);
    agg_kernel<<<(rowsTN + 7) / 8, 256>>>(b1, bufB);

    // ---- temporal attention ----
    zero_kernel<<<1, 256>>>((float4*)cs, TT * DD / 4);
    colsum_kernel<<<dim3(128, TT), 256>>>();
    attn_kernel<<<1, 256>>>(Wq, bq, Wk, bk);

    // ---- out = (sum_t attn[t] * embs_t) @ Wv + bv  (blend fused into A-load) ----
    gemm_tf32<1><<<dim3(2, (NN + 127) / 128), 256>>>(bufB, Wv, bv, (float*)d_out,
                                                     NN, DD, DD, 0, 0, nullptr, nullptr);
}

// round 13
// speedup vs baseline: 1.1755x; 1.1002x over previous
#include <cuda_runtime.h>
#include <cuda_fp16.h>
#include <math.h>
#include <stdint.h>

#define NN 30000
#define TT 4
#define FIN 256
#define HH 64
#define HEADS 4
#define DD 256
#define EE 240000
#define ETOT 270000            // EE + NN self loops
#define NEG_SLOPE 0.2f
#define NB_SCAN 118            // ceil(NN/256)
#define ESZ (TT * NN * HEADS)

// ---------------- scratch (device globals: allocation-free) ----------------
__device__ __align__(16) float g_h0[TT * NN * HH];      // xWp output (incl bp), (t,n) order
__device__ __align__(16) __half g_hph[TT * NN * DD];    // per-layer hp = h @ W  (fp16)
__device__ __align__(16) float g_bufA[TT * NN * DD];    // layer0 output (post ELU)
__device__ __align__(16) float g_bufB[TT * NN * DD];    // layer1 output (embs)
__device__ __align__(16) float g_esed[2 * ESZ];         // es at 0, ed at ESZ
__device__ __align__(16) float g_colsum[TT * DD];
__device__ float g_attn[TT];
// CSR
__device__ int g_deg[NN];
__device__ int g_off[NN];
__device__ int g_cursor[NN];
__device__ int g_part[256];
__device__ int g_srcs[ETOT];

// ---------------- utility ----------------
__global__ void zero_kernel(float4* __restrict__ p, int n4) {
    int i = blockIdx.x * blockDim.x + threadIdx.x;
    if (i < n4) p[i] = make_float4(0.f, 0.f, 0.f, 0.f);
}

__device__ __forceinline__ float eluf(float x) { return x > 0.f ? x : expm1f(x); }

// RNA rounding to tf32 is load-bearing: truncation biases the K-sum coherently
// and quadruples rel_err (measured R10). Do not remove.
__device__ __forceinline__ uint32_t f2tf32(float x) {
    uint32_t r;
    asm("cvt.rna.tf32.f32 %0, %1;" : "=r"(r) : "f"(x));
    return r;
}

__device__ __forceinline__ void mma_tf32(float* c, const uint32_t* a, const uint32_t* b) {
    asm volatile(
        "mma.sync.aligned.m16n8k8.row.col.f32.tf32.tf32.f32 "
        "{%0,%1,%2,%3}, {%4,%5,%6,%7}, {%8,%9}, {%0,%1,%2,%3};"
        : "+f"(c[0]), "+f"(c[1]), "+f"(c[2]), "+f"(c[3])
        : "r"(a[0]), "r"(a[1]), "r"(a[2]), "r"(a[3]), "r"(b[0]), "r"(b[1]));
}

// ---------------- CSR build ----------------
__global__ void hist_kernel(const int* __restrict__ ei) {
    int e = blockIdx.x * 256 + threadIdx.x;
    if (e >= ETOT) return;
    int d = (e < EE) ? ei[EE + e] : (e - EE);
    atomicAdd(&g_deg[d], 1);
}

__global__ void scan1_kernel() {
    __shared__ int sh[256];
    int tid = threadIdx.x;
    int i = blockIdx.x * 256 + tid;
    int v = (i < NN) ? g_deg[i] : 0;
    sh[tid] = v;
    __syncthreads();
#pragma unroll
    for (int off = 1; off < 256; off <<= 1) {
        int t = (tid >= off) ? sh[tid - off] : 0;
        __syncthreads();
        sh[tid] += t;
        __syncthreads();
    }
    if (i < NN) g_off[i] = sh[tid] - v;       // exclusive (local)
    if (tid == 255) g_part[blockIdx.x] = sh[255];
}

__global__ void scan2_kernel() {
    __shared__ int sh[256];
    int tid = threadIdx.x;
    int v = (tid < NB_SCAN) ? g_part[tid] : 0;
    sh[tid] = v;
    __syncthreads();
#pragma unroll
    for (int off = 1; off < 256; off <<= 1) {
        int t = (tid >= off) ? sh[tid - off] : 0;
        __syncthreads();
        sh[tid] += t;
        __syncthreads();
    }
    if (tid < NB_SCAN) g_part[tid] = sh[tid] - v;  // exclusive
}

__global__ void scan3_kernel() {
    int i = blockIdx.x * 256 + threadIdx.x;
    if (i < NN) {
        int o = g_off[i] + g_part[blockIdx.x];
        g_off[i] = o;
        g_cursor[i] = o;
    }
}

__global__ void scatter_kernel(const int* __restrict__ ei) {
    int e = blockIdx.x * 256 + threadIdx.x;
    if (e >= ETOT) return;
    int s, d;
    if (e < EE) { s = ei[e]; d = ei[EE + e]; }
    else        { s = e - EE; d = s; }
    int pos = atomicAdd(&g_cursor[d], 1);
    g_srcs[pos] = s;
}

// ---------------- tf32 tensor-core GEMM, double-buffered, fused esed / blend ----------------
// C(R x Nc) = A(R x K) @ B(K x Nc) (+bias). 128x128 tile, KTILE=16, 256 threads.
// permT!=0: output row r=(n*permT+t) -> t*permN+n.
// asrc/adst != null: accumulate per-head dots of the BIASED output row into g_esed
//                    (g_esed must be pre-zeroed).
// BLEND: A row r = sum_t g_attn[t] * A[t*SLAB + r*K + k] (A = bufB base).
// HALFC: C is __half* (hp buffer); epilogue writes __half2 pairs.
template<int BLEND, int HALFC>
__global__ void __launch_bounds__(256) gemm_tf32(
    const float* __restrict__ A, const float* __restrict__ B,
    const float* __restrict__ bias, void* __restrict__ Cv,
    int Rows, int K, int Ncols, int permT, int permN,
    const float* __restrict__ asrc, const float* __restrict__ adst)
{
    __shared__ float As[2][16][136];   // [k][row], pad -> frag bank = 8k+row (conflict-free)
    __shared__ float Bs[2][16][136];   // [k][col]
    const int tid = threadIdx.x;
    const int wid = tid >> 5;
    const int lane = tid & 31;
    const int wm = wid >> 2;        // 0..1
    const int wn = wid & 3;         // 0..3
    const int g = lane >> 2;        // 0..7
    const int t4 = lane & 3;        // 0..3
    const int rowBase = blockIdx.y << 7;
    const int colBase = blockIdx.x << 7;

    const int arow = tid >> 1;            // 0..127
    const int ak = (tid & 1) << 3;        // 0 / 8
    const int bk = wid;                   // rows bk, bk+8
    const int bcol = lane << 2;           // 0..124

    float acc[4][4][4];
#pragma unroll
    for (int mi = 0; mi < 4; mi++)
#pragma unroll
        for (int ni = 0; ni < 4; ni++)
#pragma unroll
            for (int q = 0; q < 4; q++) acc[mi][ni][q] = 0.f;

    const int gr = rowBase + arow;
    const bool aOK = gr < Rows;
    const float* Ap = A + (size_t)(aOK ? gr : 0) * K + ak;
    const bool bOK = (colBase + bcol) < Ncols;
    const float* Bp = B + (size_t)bk * Ncols + colBase + bcol;
    const size_t SLAB = (size_t)NN * DD;

    float atw0 = 0.f, atw1 = 0.f, atw2 = 0.f, atw3 = 0.f;
    if (BLEND) { atw0 = g_attn[0]; atw1 = g_attn[1]; atw2 = g_attn[2]; atw3 = g_attn[3]; }

    const int nk = K >> 4;
    float4 ra[2], rb[2];

    auto load_tile = [&](int kt) {
        const int kbase = kt << 4;
#pragma unroll
        for (int i = 0; i < 2; i++) {
            float4 v = make_float4(0.f, 0.f, 0.f, 0.f);
            if (aOK) {
                const float* p = Ap + kbase + i * 4;
                if (BLEND) {
                    float4 u0 = *(const float4*)(p);
                    float4 u1 = *(const float4*)(p + SLAB);
                    float4 u2 = *(const float4*)(p + 2 * SLAB);
                    float4 u3 = *(const float4*)(p + 3 * SLAB);
                    v.x = atw0 * u0.x + atw1 * u1.x + atw2 * u2.x + atw3 * u3.x;
                    v.y = atw0 * u0.y + atw1 * u1.y + atw2 * u2.y + atw3 * u3.y;
                    v.z = atw0 * u0.z + atw1 * u1.z + atw2 * u2.z + atw3 * u3.z;
                    v.w = atw0 * u0.w + atw1 * u1.w + atw2 * u2.w + atw3 * u3.w;
                } else {
                    v = *(const float4*)p;
                }
            }
            ra[i] = v;
            float4 w = make_float4(0.f, 0.f, 0.f, 0.f);
            if (bOK) w = *(const float4*)(Bp + (size_t)(kbase + i * 8) * Ncols);
            rb[i] = w;
        }
    };
    auto store_tile = [&](int buf) {
#pragma unroll
        for (int i = 0; i < 2; i++) {
            int kb = ak + i * 4;
            As[buf][kb + 0][arow] = __uint_as_float(f2tf32(ra[i].x));
            As[buf][kb + 1][arow] = __uint_as_float(f2tf32(ra[i].y));
            As[buf][kb + 2][arow] = __uint_as_float(f2tf32(ra[i].z));
            As[buf][kb + 3][arow] = __uint_as_float(f2tf32(ra[i].w));
            float4 w;
            w.x = __uint_as_float(f2tf32(rb[i].x));
            w.y = __uint_as_float(f2tf32(rb[i].y));
            w.z = __uint_as_float(f2tf32(rb[i].z));
            w.w = __uint_as_float(f2tf32(rb[i].w));
            *(float4*)&Bs[buf][bk + i * 8][bcol] = w;
        }
    };

    load_tile(0);
    store_tile(0);
    __syncthreads();

    for (int kt = 0; kt < nk; kt++) {
        const int buf = kt & 1;
        if (kt + 1 < nk) load_tile(kt + 1);
#pragma unroll
        for (int ks = 0; ks < 2; ks++) {
            const int k0 = ks * 8;
            uint32_t afr[4][4];
            uint32_t bfr[4][2];
#pragma unroll
            for (int mi = 0; mi < 4; mi++) {
                int row = (wm << 6) + (mi << 4) + g;
                afr[mi][0] = __float_as_uint(As[buf][k0 + t4][row]);
                afr[mi][1] = __float_as_uint(As[buf][k0 + t4][row + 8]);
                afr[mi][2] = __float_as_uint(As[buf][k0 + t4 + 4][row]);
                afr[mi][3] = __float_as_uint(As[buf][k0 + t4 + 4][row + 8]);
            }
#pragma unroll
            for (int ni = 0; ni < 4; ni++) {
                int col = (wn << 5) + (ni << 3) + g;
                bfr[ni][0] = __float_as_uint(Bs[buf][k0 + t4][col]);
                bfr[ni][1] = __float_as_uint(Bs[buf][k0 + t4 + 4][col]);
            }
#pragma unroll
            for (int mi = 0; mi < 4; mi++)
#pragma unroll
                for (int ni = 0; ni < 4; ni++)
                    mma_tf32(acc[mi][ni], afr[mi], bfr[ni]);
        }
        if (kt + 1 < nk) {
            store_tile(buf ^ 1);
            __syncthreads();
        }
    }

    // ---- epilogue: bias -> C value, store C (fp32 or fp16), fused es/ed dots ----
#pragma unroll
    for (int mi = 0; mi < 4; mi++) {
        int row0 = rowBase + (wm << 6) + (mi << 4) + g;
        int row1 = row0 + 8;
        int orow0 = -1, orow1 = -1;
        if (row0 < Rows) orow0 = permT ? ((row0 % permT) * permN + row0 / permT) : row0;
        if (row1 < Rows) orow1 = permT ? ((row1 % permT) * permN + row1 / permT) : row1;
        float es0 = 0.f, es1 = 0.f, ed0 = 0.f, ed1 = 0.f;
#pragma unroll
        for (int ni = 0; ni < 4; ni++) {
            int col = colBase + (wn << 5) + (ni << 3) + (t4 << 1);
            if (col < Ncols) {
                float bx = 0.f, by = 0.f;
                if (bias) { bx = bias[col]; by = bias[col + 1]; }
                float c00 = acc[mi][ni][0] + bx;
                float c01 = acc[mi][ni][1] + by;
                float c10 = acc[mi][ni][2] + bx;
                float c11 = acc[mi][ni][3] + by;
                if (orow0 >= 0) {
                    if (HALFC) {
                        __half2* cp = (__half2*)((__half*)Cv + (size_t)orow0 * Ncols + col);
                        *cp = __floats2half2_rn(c00, c01);
                    } else {
                        float* cp = (float*)Cv + (size_t)orow0 * Ncols + col;
                        cp[0] = c00;
                        cp[1] = c01;
                    }
                }
                if (orow1 >= 0) {
                    if (HALFC) {
                        __half2* cp = (__half2*)((__half*)Cv + (size_t)orow1 * Ncols + col);
                        *cp = __floats2half2_rn(c10, c11);
                    } else {
                        float* cp = (float*)Cv + (size_t)orow1 * Ncols + col;
                        cp[0] = c10;
                        cp[1] = c11;
                    }
                }
                if (asrc) {
                    float sx = __ldg(asrc + col), sy = __ldg(asrc + col + 1);
                    float dx = __ldg(adst + col), dy = __ldg(adst + col + 1);
                    es0 += c00 * sx + c01 * sy;
                    ed0 += c00 * dx + c01 * dy;
                    es1 += c10 * sx + c11 * sy;
                    ed1 += c10 * dx + c11 * dy;
                }
            }
        }
        if (asrc) {
            es0 += __shfl_xor_sync(0xffffffffu, es0, 1);
            es0 += __shfl_xor_sync(0xffffffffu, es0, 2);
            es1 += __shfl_xor_sync(0xffffffffu, es1, 1);
            es1 += __shfl_xor_sync(0xffffffffu, es1, 2);
            ed0 += __shfl_xor_sync(0xffffffffu, ed0, 1);
            ed0 += __shfl_xor_sync(0xffffffffu, ed0, 2);
            ed1 += __shfl_xor_sync(0xffffffffu, ed1, 1);
            ed1 += __shfl_xor_sync(0xffffffffu, ed1, 2);
            if (t4 == 0) {
                int head = (colBase + (wn << 5)) >> 6;
                if (orow0 >= 0) {
                    atomicAdd(&g_esed[(size_t)orow0 * HEADS + head], es0);
                    atomicAdd(&g_esed[ESZ + (size_t)orow0 * HEADS + head], ed0);
                }
                if (orow1 >= 0) {
                    atomicAdd(&g_esed[(size_t)orow1 * HEADS + head], es1);
                    atomicAdd(&g_esed[ESZ + (size_t)orow1 * HEADS + head], ed1);
                }
            }
        }
    }
}

// ---------------- fused softmax + aggregation, SINGLE PASS: warp per (t, dst) ----------------
// out = ELU( (sum_e w_e * hp[src]) / (z + 1e-16) + bias ),  w_e = exp(leaky(es+ed)), z = sum w_e
// hp is fp16 (g_hph): one ldg.128 per lane covers the lane's 8 columns.
__global__ void __launch_bounds__(256) agg_kernel(const float* __restrict__ bias,
                                                  float* __restrict__ out)
{
    int gw = (blockIdx.x * 256 + threadIdx.x) >> 5;
    int lane = threadIdx.x & 31;
    if (gw >= TT * NN) return;
    int t = gw / NN;
    int d = gw - t * NN;
    int base = g_off[d];
    int deg = g_deg[d];
    const size_t tN = (size_t)t * NN;
    int myh = lane >> 3;                   // head of my 8 output cols
    float edh = __ldg(g_esed + ESZ + (size_t)gw * HEADS + myh);

    float z = 0.f;
    float4 a0 = make_float4(0.f, 0.f, 0.f, 0.f);
    float4 a1 = make_float4(0.f, 0.f, 0.f, 0.f);
    for (int j = 0; j < deg; j++) {
        int s = g_srcs[base + j];
        float es = __ldg(g_esed + (tN + s) * HEADS + myh);
        float v = es + edh;
        v = v > 0.f ? v : NEG_SLOPE * v;
        float w = __expf(v);
        z += w;
        const uint4 q = __ldg((const uint4*)(g_hph + (tN + s) * DD + lane * 8));
        __half2 h0v = *reinterpret_cast<const __half2*>(&q.x);
        __half2 h1v = *reinterpret_cast<const __half2*>(&q.y);
        __half2 h2v = *reinterpret_cast<const __half2*>(&q.z);
        __half2 h3v = *reinterpret_cast<const __half2*>(&q.w);
        float2 f0 = __half22float2(h0v);
        float2 f1 = __half22float2(h1v);
        float2 f2 = __half22float2(h2v);
        float2 f3 = __half22float2(h3v);
        a0.x += w * f0.x; a0.y += w * f0.y;
        a0.z += w * f1.x; a0.w += w * f1.y;
        a1.x += w * f2.x; a1.y += w * f2.y;
        a1.z += w * f3.x; a1.w += w * f3.y;
    }
    float zinv = 1.f / (z + 1e-16f);

    // ---- epilogue: normalize + bias + ELU, single write ----
    const float4* bp4 = (const float4*)bias + lane * 2;
    float4 b0v = __ldg(bp4), b1v = __ldg(bp4 + 1);
    float4 o0, o1;
    o0.x = eluf(a0.x * zinv + b0v.x); o0.y = eluf(a0.y * zinv + b0v.y);
    o0.z = eluf(a0.z * zinv + b0v.z); o0.w = eluf(a0.w * zinv + b0v.w);
    o1.x = eluf(a1.x * zinv + b1v.x); o1.y = eluf(a1.y * zinv + b1v.y);
    o1.z = eluf(a1.z * zinv + b1v.z); o1.w = eluf(a1.w * zinv + b1v.w);
    float4* op = (float4*)(out + (size_t)gw * DD) + lane * 2;
    op[0] = o0;
    op[1] = o1;
}

// ---------------- per-t column sums of embs (bufB) ----------------
__global__ void __launch_bounds__(256) colsum_kernel()
{
    int t = blockIdx.y;
    int c = threadIdx.x;
    float s = 0.f;
    for (int n = blockIdx.x; n < NN; n += gridDim.x)
        s += g_bufB[((size_t)t * NN + n) * DD + c];
    atomicAdd(&g_colsum[t * DD + c], s);
}

// ---------------- temporal attention weights (single block) ----------------
__global__ void __launch_bounds__(256) attn_kernel(
    const float* __restrict__ Wq, const float* __restrict__ bq,
    const float* __restrict__ Wk, const float* __restrict__ bk)
{
    __shared__ float mean[TT][DD];
    __shared__ float Kt[TT][DD];
    __shared__ float Qv[DD];
    __shared__ float red[256];
    __shared__ float sc[TT];
    int c = threadIdx.x;
#pragma unroll
    for (int t = 0; t < TT; t++)
        mean[t][c] = g_colsum[t * DD + c] * (1.0f / (float)NN);
    __syncthreads();
#pragma unroll
    for (int t = 0; t < TT; t++) {
        float acc = bk[c];
        for (int f = 0; f < DD; f++) acc += mean[t][f] * Wk[f * DD + c];
        Kt[t][c] = acc;
    }
    {
        float acc = bq[c];
        for (int f = 0; f < DD; f++) acc += mean[TT - 1][f] * Wq[f * DD + c];
        Qv[c] = acc;
    }
    __syncthreads();
    for (int t = 0; t < TT; t++) {
        red[c] = Qv[c] * Kt[t][c];
        __syncthreads();
        for (int off = 128; off > 0; off >>= 1) {
            if (c < off) red[c] += red[c + off];
            __syncthreads();
        }
        if (c == 0) sc[t] = red[0] * (1.0f / 16.0f);   // 1/sqrt(256)
        __syncthreads();
    }
    if (c == 0) {
        float m = fmaxf(fmaxf(sc[0], sc[1]), fmaxf(sc[2], sc[3]));
        float w0 = expf(sc[0] - m), w1 = expf(sc[1] - m);
        float w2 = expf(sc[2] - m), w3 = expf(sc[3] - m);
        float inv = 1.0f / (w0 + w1 + w2 + w3);
        g_attn[0] = w0 * inv; g_attn[1] = w1 * inv;
        g_attn[2] = w2 * inv; g_attn[3] = w3 * inv;
    }
}

// ---------------- launch ----------------
extern "C" void kernel_launch(void* const* d_in, const int* in_sizes, int n_in,
                              void* d_out, int out_size)
{
    const float* x      = (const float*)d_in[0];
    const int*   ei     = (const int*)  d_in[1];
    const float* Wp     = (const float*)d_in[2];
    const float* bp     = (const float*)d_in[3];
    const float* W0     = (const float*)d_in[4];
    const float* a_src0 = (const float*)d_in[5];
    const float* a_dst0 = (const float*)d_in[6];
    const float* b0     = (const float*)d_in[7];
    const float* W1     = (const float*)d_in[8];
    const float* a_src1 = (const float*)d_in[9];
    const float* a_dst1 = (const float*)d_in[10];
    const float* b1     = (const float*)d_in[11];
    const float* Wq     = (const float*)d_in[12];
    const float* bq     = (const float*)d_in[13];
    const float* Wk     = (const float*)d_in[14];
    const float* bk     = (const float*)d_in[15];
    const float* Wv     = (const float*)d_in[16];
    const float* bv     = (const float*)d_in[17];

    float *h0, *bufA, *bufB, *esed, *cs;
    __half *hph;
    int *degp;
    cudaGetSymbolAddress((void**)&h0,   g_h0);
    cudaGetSymbolAddress((void**)&hph,  g_hph);
    cudaGetSymbolAddress((void**)&bufA, g_bufA);
    cudaGetSymbolAddress((void**)&bufB, g_bufB);
    cudaGetSymbolAddress((void**)&esed, g_esed);
    cudaGetSymbolAddress((void**)&cs,   g_colsum);
    cudaGetSymbolAddress((void**)&degp, g_deg);

    const int rowsTN = TT * NN;            // 120000
    const int edges  = ETOT;               // 270000
    const int gy = (rowsTN + 127) / 128;   // 938
    const int esed4 = 2 * ESZ / 4;         // 480000

    // ---- CSR build (graph shared across t and both layers) ----
    zero_kernel<<<(NN / 4 + 255) / 256, 256>>>((float4*)degp, NN / 4);
    hist_kernel<<<(edges + 255) / 256, 256>>>(ei);
    scan1_kernel<<<NB_SCAN, 256>>>();
    scan2_kernel<<<1, 256>>>();
    scan3_kernel<<<NB_SCAN, 256>>>();
    scatter_kernel<<<(edges + 255) / 256, 256>>>(ei);

    // ---- h0(t,n) = x[n,t] @ Wp + bp  (64-wide, bias folded here, perm output) ----
    gemm_tf32<0, 0><<<dim3(1, gy), 256>>>(x, Wp, bp, h0, rowsTN, FIN, HH,
                                          TT, NN, nullptr, nullptr);

    // ---- GAT layer 0: hp = h0 @ W0 (K=64, fp16 out), es/ed fused on outputs ----
    zero_kernel<<<(esed4 + 255) / 256, 256>>>((float4*)esed, esed4);
    gemm_tf32<0, 1><<<dim3(2, gy), 256>>>(h0, W0, nullptr, hph, rowsTN, HH, DD,
                                          0, 0, a_src0, a_dst0);
    agg_kernel<<<(rowsTN + 7) / 8, 256>>>(b0, bufA);

    // ---- GAT layer 1 ----
    zero_kernel<<<(esed4 + 255) / 256, 256>>>((float4*)esed, esed4);
    gemm_tf32<0, 1><<<dim3(2, gy), 256>>>(bufA, W1, nullptr, hph, rowsTN, DD, DD,
                                          0, 0, a_src1, a_dst1);
    agg_kernel<<<(rowsTN + 7) / 8, 256>>>(b1, bufB);

    // ---- temporal attention ----
    zero_kernel<<<1, 256>>>((float4*)cs, TT * DD / 4);
    colsum_kernel<<<dim3(128, TT), 256>>>();
    attn_kernel<<<1, 256>>>(Wq, bq, Wk, bk);

    // ---- out = (sum_t attn[t] * embs_t) @ Wv + bv  (blend fused into A-load) ----
    gemm_tf32<1, 0><<<dim3(2, (NN + 127) / 128), 256>>>(bufB, Wv, bv, (float*)d_out,
                                                        NN, DD, DD, 0, 0, nullptr, nullptr);
}

// round 14
// speedup vs baseline: 1.1935x; 1.0153x over previous
#include <cuda_runtime.h>
#include <cuda_fp16.h>
#include <math.h>
#include <stdint.h>

#define NN 30000
#define TT 4
#define FIN 256
#define HH 64
#define HEADS 4
#define DD 256
#define EE 240000
#define ETOT 270000            // EE + NN self loops
#define NEG_SLOPE 0.2f
#define NB_SCAN 118            // ceil(NN/256)
#define ESZ (TT * NN * HEADS)

// ---------------- scratch (device globals: allocation-free) ----------------
__device__ __align__(16) float  g_h0[TT * NN * HH];     // xWp output (incl bp), (t,n) order
__device__ __align__(16) __half g_hph[TT * NN * DD];    // per-layer hp = h @ W  (fp16)
__device__ __align__(16) __half g_bufAh[TT * NN * DD];  // layer0 output (post ELU, fp16)
__device__ __align__(16) __half g_bufBh[TT * NN * DD];  // layer1 output (embs, fp16)
__device__ __align__(16) float  g_esed[2 * ESZ];        // es at 0, ed at ESZ
__device__ __align__(16) float  g_colsum[TT * DD];
__device__ float g_attn[TT];
// CSR
__device__ int g_deg[NN];
__device__ int g_off[NN];
__device__ int g_cursor[NN];
__device__ int g_part[256];
__device__ int g_srcs[ETOT];

// ---------------- utility ----------------
__global__ void zero_kernel(float4* __restrict__ p, int n4) {
    int i = blockIdx.x * blockDim.x + threadIdx.x;
    if (i < n4) p[i] = make_float4(0.f, 0.f, 0.f, 0.f);
}

__device__ __forceinline__ float eluf(float x) { return x > 0.f ? x : expm1f(x); }

// RNA rounding to tf32 is load-bearing: truncation biases the K-sum coherently
// and quadruples rel_err (measured R10). Do not remove.
// fp16 storage of GEMM A-inputs is exact under this rounding (both 10-bit mantissa).
__device__ __forceinline__ uint32_t f2tf32(float x) {
    uint32_t r;
    asm("cvt.rna.tf32.f32 %0, %1;" : "=r"(r) : "f"(x));
    return r;
}

__device__ __forceinline__ void mma_tf32(float* c, const uint32_t* a, const uint32_t* b) {
    asm volatile(
        "mma.sync.aligned.m16n8k8.row.col.f32.tf32.tf32.f32 "
        "{%0,%1,%2,%3}, {%4,%5,%6,%7}, {%8,%9}, {%0,%1,%2,%3};"
        : "+f"(c[0]), "+f"(c[1]), "+f"(c[2]), "+f"(c[3])
        : "r"(a[0]), "r"(a[1]), "r"(a[2]), "r"(a[3]), "r"(b[0]), "r"(b[1]));
}

__device__ __forceinline__ float4 half8_lo4(uint2 q) {
    __half2 ha = *reinterpret_cast<__half2*>(&q.x);
    __half2 hb = *reinterpret_cast<__half2*>(&q.y);
    float2 fa = __half22float2(ha), fb = __half22float2(hb);
    return make_float4(fa.x, fa.y, fb.x, fb.y);
}

// ---------------- CSR build ----------------
__global__ void hist_kernel(const int* __restrict__ ei) {
    int e = blockIdx.x * 256 + threadIdx.x;
    if (e >= ETOT) return;
    int d = (e < EE) ? ei[EE + e] : (e - EE);
    atomicAdd(&g_deg[d], 1);
}

__global__ void scan1_kernel() {
    __shared__ int sh[256];
    int tid = threadIdx.x;
    int i = blockIdx.x * 256 + tid;
    int v = (i < NN) ? g_deg[i] : 0;
    sh[tid] = v;
    __syncthreads();
#pragma unroll
    for (int off = 1; off < 256; off <<= 1) {
        int t = (tid >= off) ? sh[tid - off] : 0;
        __syncthreads();
        sh[tid] += t;
        __syncthreads();
    }
    if (i < NN) g_off[i] = sh[tid] - v;       // exclusive (local)
    if (tid == 255) g_part[blockIdx.x] = sh[255];
}

__global__ void scan2_kernel() {
    __shared__ int sh[256];
    int tid = threadIdx.x;
    int v = (tid < NB_SCAN) ? g_part[tid] : 0;
    sh[tid] = v;
    __syncthreads();
#pragma unroll
    for (int off = 1; off < 256; off <<= 1) {
        int t = (tid >= off) ? sh[tid - off] : 0;
        __syncthreads();
        sh[tid] += t;
        __syncthreads();
    }
    if (tid < NB_SCAN) g_part[tid] = sh[tid] - v;  // exclusive
}

__global__ void scan3_kernel() {
    int i = blockIdx.x * 256 + threadIdx.x;
    if (i < NN) {
        int o = g_off[i] + g_part[blockIdx.x];
        g_off[i] = o;
        g_cursor[i] = o;
    }
}

__global__ void scatter_kernel(const int* __restrict__ ei) {
    int e = blockIdx.x * 256 + threadIdx.x;
    if (e >= ETOT) return;
    int s, d;
    if (e < EE) { s = ei[e]; d = ei[EE + e]; }
    else        { s = e - EE; d = s; }
    int pos = atomicAdd(&g_cursor[d], 1);
    g_srcs[pos] = s;
}

// ---------------- tf32 tensor-core GEMM, double-buffered, fused esed / blend ----------------
// C(R x Nc) = A(R x K) @ B(K x Nc) (+bias). 128x128 tile, KTILE=16, 256 threads.
// permT!=0: output row r=(n*permT+t) -> t*permN+n.
// asrc/adst != null: accumulate per-head dots of the BIASED output row into g_esed.
// BLEND: A row r = sum_t g_attn[t] * A[t*SLAB + r*K + k].
// AHALF: A is __half*.  HALFC: C is __half*.
template<int BLEND, int AHALF, int HALFC>
__global__ void __launch_bounds__(256) gemm_tf32(
    const void* __restrict__ Av, const float* __restrict__ B,
    const float* __restrict__ bias, void* __restrict__ Cv,
    int Rows, int K, int Ncols, int permT, int permN,
    const float* __restrict__ asrc, const float* __restrict__ adst)
{
    __shared__ float As[2][16][136];   // [k][row], pad -> frag bank = 8k+row (conflict-free)
    __shared__ float Bs[2][16][136];   // [k][col]
    const int tid = threadIdx.x;
    const int wid = tid >> 5;
    const int lane = tid & 31;
    const int wm = wid >> 2;        // 0..1
    const int wn = wid & 3;         // 0..3
    const int g = lane >> 2;        // 0..7
    const int t4 = lane & 3;        // 0..3
    const int rowBase = blockIdx.y << 7;
    const int colBase = blockIdx.x << 7;

    const int arow = tid >> 1;            // 0..127
    const int ak = (tid & 1) << 3;        // 0 / 8
    const int bk = wid;                   // rows bk, bk+8
    const int bcol = lane << 2;           // 0..124

    float acc[4][4][4];
#pragma unroll
    for (int mi = 0; mi < 4; mi++)
#pragma unroll
        for (int ni = 0; ni < 4; ni++)
#pragma unroll
            for (int q = 0; q < 4; q++) acc[mi][ni][q] = 0.f;

    const int gr = rowBase + arow;
    const bool aOK = gr < Rows;
    const size_t aoff = (size_t)(aOK ? gr : 0) * K + ak;
    const float*  Apf = (const float*)Av + aoff;
    const __half* Aph = (const __half*)Av + aoff;
    const bool bOK = (colBase + bcol) < Ncols;
    const float* Bp = B + (size_t)bk * Ncols + colBase + bcol;
    const size_t SLAB = (size_t)NN * DD;

    float atw0 = 0.f, atw1 = 0.f, atw2 = 0.f, atw3 = 0.f;
    if (BLEND) { atw0 = g_attn[0]; atw1 = g_attn[1]; atw2 = g_attn[2]; atw3 = g_attn[3]; }

    const int nk = K >> 4;
    float4 ra[2], rb[2];

    auto load_tile = [&](int kt) {
        const int kbase = kt << 4;
#pragma unroll
        for (int i = 0; i < 2; i++) {
            float4 v = make_float4(0.f, 0.f, 0.f, 0.f);
            if (aOK) {
                if (AHALF) {
                    const __half* p = Aph + kbase + i * 4;
                    if (BLEND) {
                        float4 u0 = half8_lo4(*(const uint2*)(p));
                        float4 u1 = half8_lo4(*(const uint2*)(p + SLAB));
                        float4 u2 = half8_lo4(*(const uint2*)(p + 2 * SLAB));
                        float4 u3 = half8_lo4(*(const uint2*)(p + 3 * SLAB));
                        v.x = atw0 * u0.x + atw1 * u1.x + atw2 * u2.x + atw3 * u3.x;
                        v.y = atw0 * u0.y + atw1 * u1.y + atw2 * u2.y + atw3 * u3.y;
                        v.z = atw0 * u0.z + atw1 * u1.z + atw2 * u2.z + atw3 * u3.z;
                        v.w = atw0 * u0.w + atw1 * u1.w + atw2 * u2.w + atw3 * u3.w;
                    } else {
                        v = half8_lo4(*(const uint2*)p);
                    }
                } else {
                    const float* p = Apf + kbase + i * 4;
                    if (BLEND) {
                        float4 u0 = *(const float4*)(p);
                        float4 u1 = *(const float4*)(p + SLAB);
                        float4 u2 = *(const float4*)(p + 2 * SLAB);
                        float4 u3 = *(const float4*)(p + 3 * SLAB);
                        v.x = atw0 * u0.x + atw1 * u1.x + atw2 * u2.x + atw3 * u3.x;
                        v.y = atw0 * u0.y + atw1 * u1.y + atw2 * u2.y + atw3 * u3.y;
                        v.z = atw0 * u0.z + atw1 * u1.z + atw2 * u2.z + atw3 * u3.z;
                        v.w = atw0 * u0.w + atw1 * u1.w + atw2 * u2.w + atw3 * u3.w;
                    } else {
                        v = *(const float4*)p;
                    }
                }
            }
            ra[i] = v;
            float4 w = make_float4(0.f, 0.f, 0.f, 0.f);
            if (bOK) w = *(const float4*)(Bp + (size_t)(kbase + i * 8) * Ncols);
            rb[i] = w;
        }
    };
    auto store_tile = [&](int buf) {
#pragma unroll
        for (int i = 0; i < 2; i++) {
            int kb = ak + i * 4;
            As[buf][kb + 0][arow] = __uint_as_float(f2tf32(ra[i].x));
            As[buf][kb + 1][arow] = __uint_as_float(f2tf32(ra[i].y));
            As[buf][kb + 2][arow] = __uint_as_float(f2tf32(ra[i].z));
            As[buf][kb + 3][arow] = __uint_as_float(f2tf32(ra[i].w));
            float4 w;
            w.x = __uint_as_float(f2tf32(rb[i].x));
            w.y = __uint_as_float(f2tf32(rb[i].y));
            w.z = __uint_as_float(f2tf32(rb[i].z));
            w.w = __uint_as_float(f2tf32(rb[i].w));
            *(float4*)&Bs[buf][bk + i * 8][bcol] = w;
        }
    };

    load_tile(0);
    store_tile(0);
    __syncthreads();

    for (int kt = 0; kt < nk; kt++) {
        const int buf = kt & 1;
        if (kt + 1 < nk) load_tile(kt + 1);
#pragma unroll
        for (int ks = 0; ks < 2; ks++) {
            const int k0 = ks * 8;
            uint32_t afr[4][4];
            uint32_t bfr[4][2];
#pragma unroll
            for (int mi = 0; mi < 4; mi++) {
                int row = (wm << 6) + (mi << 4) + g;
                afr[mi][0] = __float_as_uint(As[buf][k0 + t4][row]);
                afr[mi][1] = __float_as_uint(As[buf][k0 + t4][row + 8]);
                afr[mi][2] = __float_as_uint(As[buf][k0 + t4 + 4][row]);
                afr[mi][3] = __float_as_uint(As[buf][k0 + t4 + 4][row + 8]);
            }
#pragma unroll
            for (int ni = 0; ni < 4; ni++) {
                int col = (wn << 5) + (ni << 3) + g;
                bfr[ni][0] = __float_as_uint(Bs[buf][k0 + t4][col]);
                bfr[ni][1] = __float_as_uint(Bs[buf][k0 + t4 + 4][col]);
            }
#pragma unroll
            for (int mi = 0; mi < 4; mi++)
#pragma unroll
                for (int ni = 0; ni < 4; ni++)
                    mma_tf32(acc[mi][ni], afr[mi], bfr[ni]);
        }
        if (kt + 1 < nk) {
            store_tile(buf ^ 1);
            __syncthreads();
        }
    }

    // ---- epilogue: bias -> C value, store C (fp32 or fp16), fused es/ed dots ----
#pragma unroll
    for (int mi = 0; mi < 4; mi++) {
        int row0 = rowBase + (wm << 6) + (mi << 4) + g;
        int row1 = row0 + 8;
        int orow0 = -1, orow1 = -1;
        if (row0 < Rows) orow0 = permT ? ((row0 % permT) * permN + row0 / permT) : row0;
        if (row1 < Rows) orow1 = permT ? ((row1 % permT) * permN + row1 / permT) : row1;
        float es0 = 0.f, es1 = 0.f, ed0 = 0.f, ed1 = 0.f;
#pragma unroll
        for (int ni = 0; ni < 4; ni++) {
            int col = colBase + (wn << 5) + (ni << 3) + (t4 << 1);
            if (col < Ncols) {
                float bx = 0.f, by = 0.f;
                if (bias) { bx = bias[col]; by = bias[col + 1]; }
                float c00 = acc[mi][ni][0] + bx;
                float c01 = acc[mi][ni][1] + by;
                float c10 = acc[mi][ni][2] + bx;
                float c11 = acc[mi][ni][3] + by;
                if (orow0 >= 0) {
                    if (HALFC) {
                        __half2* cp = (__half2*)((__half*)Cv + (size_t)orow0 * Ncols + col);
                        *cp = __floats2half2_rn(c00, c01);
                    } else {
                        float* cp = (float*)Cv + (size_t)orow0 * Ncols + col;
                        cp[0] = c00;
                        cp[1] = c01;
                    }
                }
                if (orow1 >= 0) {
                    if (HALFC) {
                        __half2* cp = (__half2*)((__half*)Cv + (size_t)orow1 * Ncols + col);
                        *cp = __floats2half2_rn(c10, c11);
                    } else {
                        float* cp = (float*)Cv + (size_t)orow1 * Ncols + col;
                        cp[0] = c10;
                        cp[1] = c11;
                    }
                }
                if (asrc) {
                    float sx = __ldg(asrc + col), sy = __ldg(asrc + col + 1);
                    float dx = __ldg(adst + col), dy = __ldg(adst + col + 1);
                    es0 += c00 * sx + c01 * sy;
                    ed0 += c00 * dx + c01 * dy;
                    es1 += c10 * sx + c11 * sy;
                    ed1 += c10 * dx + c11 * dy;
                }
            }
        }
        if (asrc) {
            es0 += __shfl_xor_sync(0xffffffffu, es0, 1);
            es0 += __shfl_xor_sync(0xffffffffu, es0, 2);
            es1 += __shfl_xor_sync(0xffffffffu, es1, 1);
            es1 += __shfl_xor_sync(0xffffffffu, es1, 2);
            ed0 += __shfl_xor_sync(0xffffffffu, ed0, 1);
            ed0 += __shfl_xor_sync(0xffffffffu, ed0, 2);
            ed1 += __shfl_xor_sync(0xffffffffu, ed1, 1);
            ed1 += __shfl_xor_sync(0xffffffffu, ed1, 2);
            if (t4 == 0) {
                int head = (colBase + (wn << 5)) >> 6;
                if (orow0 >= 0) {
                    atomicAdd(&g_esed[(size_t)orow0 * HEADS + head], es0);
                    atomicAdd(&g_esed[ESZ + (size_t)orow0 * HEADS + head], ed0);
                }
                if (orow1 >= 0) {
                    atomicAdd(&g_esed[(size_t)orow1 * HEADS + head], es1);
                    atomicAdd(&g_esed[ESZ + (size_t)orow1 * HEADS + head], ed1);
                }
            }
        }
    }
}

// ---------------- fused softmax + aggregation, SINGLE PASS: warp per (t, dst) ----------------
// out = ELU( (sum_e w_e * hp[src]) / (z + 1e-16) + bias ),  fp16 in (g_hph), fp16 out.
__global__ void __launch_bounds__(256) agg_kernel(const float* __restrict__ bias,
                                                  __half* __restrict__ out)
{
    int gw = (blockIdx.x * 256 + threadIdx.x) >> 5;
    int lane = threadIdx.x & 31;
    if (gw >= TT * NN) return;
    int t = gw / NN;
    int d = gw - t * NN;
    int base = g_off[d];
    int deg = g_deg[d];
    const size_t tN = (size_t)t * NN;
    int myh = lane >> 3;                   // head of my 8 output cols
    float edh = __ldg(g_esed + ESZ + (size_t)gw * HEADS + myh);

    float z = 0.f;
    float4 a0 = make_float4(0.f, 0.f, 0.f, 0.f);
    float4 a1 = make_float4(0.f, 0.f, 0.f, 0.f);
    for (int j = 0; j < deg; j++) {
        int s = g_srcs[base + j];
        float es = __ldg(g_esed + (tN + s) * HEADS + myh);
        float v = es + edh;
        v = v > 0.f ? v : NEG_SLOPE * v;
        float w = __expf(v);
        z += w;
        const uint4 q = __ldg((const uint4*)(g_hph + (tN + s) * DD + lane * 8));
        float2 f0 = __half22float2(*reinterpret_cast<const __half2*>(&q.x));
        float2 f1 = __half22float2(*reinterpret_cast<const __half2*>(&q.y));
        float2 f2 = __half22float2(*reinterpret_cast<const __half2*>(&q.z));
        float2 f3 = __half22float2(*reinterpret_cast<const __half2*>(&q.w));
        a0.x += w * f0.x; a0.y += w * f0.y;
        a0.z += w * f1.x; a0.w += w * f1.y;
        a1.x += w * f2.x; a1.y += w * f2.y;
        a1.z += w * f3.x; a1.w += w * f3.y;
    }
    float zinv = 1.f / (z + 1e-16f);

    // ---- epilogue: normalize + bias + ELU, single fp16 write ----
    const float4* bp4 = (const float4*)bias + lane * 2;
    float4 b0v = __ldg(bp4), b1v = __ldg(bp4 + 1);
    uint4 o;
    __half2 h0o = __floats2half2_rn(eluf(a0.x * zinv + b0v.x), eluf(a0.y * zinv + b0v.y));
    __half2 h1o = __floats2half2_rn(eluf(a0.z * zinv + b0v.z), eluf(a0.w * zinv + b0v.w));
    __half2 h2o = __floats2half2_rn(eluf(a1.x * zinv + b1v.x), eluf(a1.y * zinv + b1v.y));
    __half2 h3o = __floats2half2_rn(eluf(a1.z * zinv + b1v.z), eluf(a1.w * zinv + b1v.w));
    o.x = *reinterpret_cast<uint32_t*>(&h0o);
    o.y = *reinterpret_cast<uint32_t*>(&h1o);
    o.z = *reinterpret_cast<uint32_t*>(&h2o);
    o.w = *reinterpret_cast<uint32_t*>(&h3o);
    *(uint4*)(out + (size_t)gw * DD + lane * 8) = o;
}

// ---------------- per-t column sums of embs (bufBh, fp16) ----------------
__global__ void __launch_bounds__(256) colsum_kernel()
{
    int t = blockIdx.y;
    int c = threadIdx.x;
    float s = 0.f;
    for (int n = blockIdx.x; n < NN; n += gridDim.x)
        s += __half2float(g_bufBh[((size_t)t * NN + n) * DD + c]);
    atomicAdd(&g_colsum[t * DD + c], s);
}

// ---------------- temporal attention weights (single block) ----------------
__global__ void __launch_bounds__(256) attn_kernel(
    const float* __restrict__ Wq, const float* __restrict__ bq,
    const float* __restrict__ Wk, const float* __restrict__ bk)
{
    __shared__ float mean[TT][DD];
    __shared__ float Kt[TT][DD];
    __shared__ float Qv[DD];
    __shared__ float red[256];
    __shared__ float sc[TT];
    int c = threadIdx.x;
#pragma unroll
    for (int t = 0; t < TT; t++)
        mean[t][c] = g_colsum[t * DD + c] * (1.0f / (float)NN);
    __syncthreads();
#pragma unroll
    for (int t = 0; t < TT; t++) {
        float acc = bk[c];
        for (int f = 0; f < DD; f++) acc += mean[t][f] * Wk[f * DD + c];
        Kt[t][c] = acc;
    }
    {
        float acc = bq[c];
        for (int f = 0; f < DD; f++) acc += mean[TT - 1][f] * Wq[f * DD + c];
        Qv[c] = acc;
    }
    __syncthreads();
    for (int t = 0; t < TT; t++) {
        red[c] = Qv[c] * Kt[t][c];
        __syncthreads();
        for (int off = 128; off > 0; off >>= 1) {
            if (c < off) red[c] += red[c + off];
            __syncthreads();
        }
        if (c == 0) sc[t] = red[0] * (1.0f / 16.0f);   // 1/sqrt(256)
        __syncthreads();
    }
    if (c == 0) {
        float m = fmaxf(fmaxf(sc[0], sc[1]), fmaxf(sc[2], sc[3]));
        float w0 = expf(sc[0] - m), w1 = expf(sc[1] - m);
        float w2 = expf(sc[2] - m), w3 = expf(sc[3] - m);
        float inv = 1.0f / (w0 + w1 + w2 + w3);
        g_attn[0] = w0 * inv; g_attn[1] = w1 * inv;
        g_attn[2] = w2 * inv; g_attn[3] = w3 * inv;
    }
}

// ---------------- launch ----------------
extern "C" void kernel_launch(void* const* d_in, const int* in_sizes, int n_in,
                              void* d_out, int out_size)
{
    const float* x      = (const float*)d_in[0];
    const int*   ei     = (const int*)  d_in[1];
    const float* Wp     = (const float*)d_in[2];
    const float* bp     = (const float*)d_in[3];
    const float* W0     = (const float*)d_in[4];
    const float* a_src0 = (const float*)d_in[5];
    const float* a_dst0 = (const float*)d_in[6];
    const float* b0     = (const float*)d_in[7];
    const float* W1     = (const float*)d_in[8];
    const float* a_src1 = (const float*)d_in[9];
    const float* a_dst1 = (const float*)d_in[10];
    const float* b1     = (const float*)d_in[11];
    const float* Wq     = (const float*)d_in[12];
    const float* bq     = (const float*)d_in[13];
    const float* Wk     = (const float*)d_in[14];
    const float* bk     = (const float*)d_in[15];
    const float* Wv     = (const float*)d_in[16];
    const float* bv     = (const float*)d_in[17];

    float *h0, *esed, *cs;
    __half *hph, *bufAh, *bufBh;
    int *degp;
    cudaGetSymbolAddress((void**)&h0,    g_h0);
    cudaGetSymbolAddress((void**)&hph,   g_hph);
    cudaGetSymbolAddress((void**)&bufAh, g_bufAh);
    cudaGetSymbolAddress((void**)&bufBh, g_bufBh);
    cudaGetSymbolAddress((void**)&esed,  g_esed);
    cudaGetSymbolAddress((void**)&cs,    g_colsum);
    cudaGetSymbolAddress((void**)&degp,  g_deg);

    const int rowsTN = TT * NN;            // 120000
    const int edges  = ETOT;               // 270000
    const int gy = (rowsTN + 127) / 128;   // 938
    const int esed4 = 2 * ESZ / 4;         // 480000

    // ---- CSR build (graph shared across t and both layers) ----
    zero_kernel<<<(NN / 4 + 255) / 256, 256>>>((float4*)degp, NN / 4);
    hist_kernel<<<(edges + 255) / 256, 256>>>(ei);
    scan1_kernel<<<NB_SCAN, 256>>>();
    scan2_kernel<<<1, 256>>>();
    scan3_kernel<<<NB_SCAN, 256>>>();
    scatter_kernel<<<(edges + 255) / 256, 256>>>(ei);

    // ---- h0(t,n) = x[n,t] @ Wp + bp  (64-wide, bias folded here, perm output) ----
    gemm_tf32<0, 0, 0><<<dim3(1, gy), 256>>>(x, Wp, bp, h0, rowsTN, FIN, HH,
                                             TT, NN, nullptr, nullptr);

    // ---- GAT layer 0: hp = h0 @ W0 (K=64, fp16 out), es/ed fused ----
    zero_kernel<<<(esed4 + 255) / 256, 256>>>((float4*)esed, esed4);
    gemm_tf32<0, 0, 1><<<dim3(2, gy), 256>>>(h0, W0, nullptr, hph, rowsTN, HH, DD,
                                             0, 0, a_src0, a_dst0);
    agg_kernel<<<(rowsTN + 7) / 8, 256>>>(b0, bufAh);

    // ---- GAT layer 1 (fp16 A in, fp16 hp out) ----
    zero_kernel<<<(esed4 + 255) / 256, 256>>>((float4*)esed, esed4);
    gemm_tf32<0, 1, 1><<<dim3(2, gy), 256>>>(bufAh, W1, nullptr, hph, rowsTN, DD, DD,
                                             0, 0, a_src1, a_dst1);
    agg_kernel<<<(rowsTN + 7) / 8, 256>>>(b1, bufBh);

    // ---- temporal attention ----
    zero_kernel<<<1, 256>>>((float4*)cs, TT * DD / 4);
    colsum_kernel<<<dim3(128, TT), 256>>>();
    attn_kernel<<<1, 256>>>(Wq, bq, Wk, bk);

    // ---- out = (sum_t attn[t] * embs_t) @ Wv + bv  (blend fused, fp16 A) ----
    gemm_tf32<1, 1, 0><<<dim3(2, (NN + 127) / 128), 256>>>(bufBh, Wv, bv, (float*)d_out,
                                                           NN, DD, DD, 0, 0, nullptr, nullptr);
}

// round 15
// speedup vs baseline: 1.3401x; 1.1229x over previous
#include <cuda_runtime.h>
#include <cuda_fp16.h>
#include <math.h>
#include <stdint.h>

#define NN 30000
#define TT 4
#define FIN 256
#define HH 64
#define HEADS 4
#define DD 256
#define EE 240000
#define ETOT 270000            // EE + NN self loops
#define NEG_SLOPE 0.2f
#define NB_SCAN 118            // ceil(NN/256)
#define ESZ (TT * NN * HEADS)

// ---------------- scratch (device globals: allocation-free) ----------------
__device__ __align__(16) float  g_h0[TT * NN * HH];     // xWp output (incl bp), (t,n) order
__device__ __align__(16) __half g_hph[TT * NN * DD];    // per-layer hp = h @ W  (fp16)
__device__ __align__(16) __half g_bufAh[TT * NN * DD];  // layer0 output (post ELU, fp16)
__device__ __align__(16) __half g_bufBh[TT * NN * DD];  // layer1 output (embs, fp16)
__device__ __align__(16) float  g_esed[2 * ESZ];        // es at 0, ed at ESZ
__device__ __align__(16) float  g_colsum[TT * DD];
__device__ float g_attn[TT];
// fp16 transposed weights: Wt[c][k] = W[k][c]
__device__ __align__(16) __half g_Wpt[HH * FIN];        // [64][256]
__device__ __align__(16) __half g_W0t[DD * HH];         // [256][64]
__device__ __align__(16) __half g_W1t[DD * DD];
__device__ __align__(16) __half g_Wvt[DD * DD];
// CSR
__device__ int g_deg[NN];
__device__ int g_off[NN];
__device__ int g_cursor[NN];
__device__ int g_part[256];
__device__ int g_srcs[ETOT];

// ---------------- utility ----------------
__global__ void zero_kernel(float4* __restrict__ p, int n4) {
    int i = blockIdx.x * blockDim.x + threadIdx.x;
    if (i < n4) p[i] = make_float4(0.f, 0.f, 0.f, 0.f);
}

__device__ __forceinline__ float eluf(float x) { return x > 0.f ? x : expm1f(x); }

// fp16 HMMA m16n8k16, fp32 accumulate. fp16 mantissa == tf32 mantissa (10 bits),
// so precision matches the tf32 path (measured 2.6-2.8e-4) while doubling MMA rate.
__device__ __forceinline__ void mma_f16(float* c, const uint32_t* a, const uint32_t* b) {
    asm volatile(
        "mma.sync.aligned.m16n8k16.row.col.f32.f16.f16.f32 "
        "{%0,%1,%2,%3}, {%4,%5,%6,%7}, {%8,%9}, {%0,%1,%2,%3};"
        : "+f"(c[0]), "+f"(c[1]), "+f"(c[2]), "+f"(c[3])
        : "r"(a[0]), "r"(a[1]), "r"(a[2]), "r"(a[3]), "r"(b[0]), "r"(b[1]));
}

// ---------------- weight prep: fp16 transpose Wt[c][k] = W[k][c] ----------------
__global__ void wprep_kernel(const float* __restrict__ Wp, const float* __restrict__ W0,
                             const float* __restrict__ W1, const float* __restrict__ Wv)
{
    int idx = blockIdx.x * 256 + threadIdx.x;
    if (idx < FIN * HH) {                       // Wp: [256][64] -> Wpt[64][256]
        int k = idx / HH, c = idx % HH;
        g_Wpt[c * FIN + k] = __float2half(Wp[idx]);
        return;
    }
    idx -= FIN * HH;
    if (idx < HH * DD) {                        // W0: [64][256] -> W0t[256][64]
        int k = idx / DD, c = idx % DD;
        g_W0t[c * HH + k] = __float2half(W0[idx]);
        return;
    }
    idx -= HH * DD;
    if (idx < DD * DD) {                        // W1
        int k = idx / DD, c = idx % DD;
        g_W1t[c * DD + k] = __float2half(W1[idx]);
        return;
    }
    idx -= DD * DD;
    if (idx < DD * DD) {                        // Wv
        int k = idx / DD, c = idx % DD;
        g_Wvt[c * DD + k] = __float2half(Wv[idx]);
    }
}

// ---------------- CSR build ----------------
__global__ void hist_kernel(const int* __restrict__ ei) {
    int e = blockIdx.x * 256 + threadIdx.x;
    if (e >= ETOT) return;
    int d = (e < EE) ? ei[EE + e] : (e - EE);
    atomicAdd(&g_deg[d], 1);
}

__global__ void scan1_kernel() {
    __shared__ int sh[256];
    int tid = threadIdx.x;
    int i = blockIdx.x * 256 + tid;
    int v = (i < NN) ? g_deg[i] : 0;
    sh[tid] = v;
    __syncthreads();
#pragma unroll
    for (int off = 1; off < 256; off <<= 1) {
        int t = (tid >= off) ? sh[tid - off] : 0;
        __syncthreads();
        sh[tid] += t;
        __syncthreads();
    }
    if (i < NN) g_off[i] = sh[tid] - v;       // exclusive (local)
    if (tid == 255) g_part[blockIdx.x] = sh[255];
}

__global__ void scan2_kernel() {
    __shared__ int sh[256];
    int tid = threadIdx.x;
    int v = (tid < NB_SCAN) ? g_part[tid] : 0;
    sh[tid] = v;
    __syncthreads();
#pragma unroll
    for (int off = 1; off < 256; off <<= 1) {
        int t = (tid >= off) ? sh[tid - off] : 0;
        __syncthreads();
        sh[tid] += t;
        __syncthreads();
    }
    if (tid < NB_SCAN) g_part[tid] = sh[tid] - v;  // exclusive
}

__global__ void scan3_kernel() {
    int i = blockIdx.x * 256 + threadIdx.x;
    if (i < NN) {
        int o = g_off[i] + g_part[blockIdx.x];
        g_off[i] = o;
        g_cursor[i] = o;
    }
}

__global__ void scatter_kernel(const int* __restrict__ ei) {
    int e = blockIdx.x * 256 + threadIdx.x;
    if (e >= ETOT) return;
    int s, d;
    if (e < EE) { s = ei[e]; d = ei[EE + e]; }
    else        { s = e - EE; d = s; }
    int pos = atomicAdd(&g_cursor[d], 1);
    g_srcs[pos] = s;
}

// ---------------- fp16 tensor-core GEMM, double-buffered, fused esed / blend ----------------
// C(R x Nc) = A(R x K) @ B(K x Nc) (+bias). 128x128 tile, KTILE=16, 256 threads.
// Bt is half, pre-transposed [Ncols][K]. K multiple of 16.
// permT!=0: output row r=(n*permT+t) -> t*permN+n.
// asrc/adst != null: per-head dots of the BIASED output row -> g_esed (pre-zeroed).
// BLEND (requires AHALF): A row r = sum_t g_attn[t] * A[t*SLAB + r*K + k].
// AHALF: A is __half*.  HALFC: C is __half*.
template<int BLEND, int AHALF, int HALFC>
__global__ void __launch_bounds__(256) gemm_f16(
    const void* __restrict__ Av, const __half* __restrict__ Bt,
    const float* __restrict__ bias, void* __restrict__ Cv,
    int Rows, int K, int Ncols, int permT, int permN,
    const float* __restrict__ asrc, const float* __restrict__ adst)
{
    __shared__ __half Ash[2][128][24];   // [row][k], 16 used + 8 pad -> frag word row*12+t4, conflict-free
    __shared__ __half Bsh[2][128][24];   // [col][k]
    const int tid = threadIdx.x;
    const int wid = tid >> 5;
    const int lane = tid & 31;
    const int wm = wid >> 2;        // 0..1
    const int wn = wid & 3;         // 0..3
    const int g = lane >> 2;        // 0..7
    const int t4 = lane & 3;        // 0..3
    const int rowBase = blockIdx.y << 7;
    const int colBase = blockIdx.x << 7;

    const int arow = tid >> 1;            // 0..127 (also B col index)
    const int ak8 = (tid & 1) << 3;       // 0 / 8

    float acc[4][4][4];
#pragma unroll
    for (int mi = 0; mi < 4; mi++)
#pragma unroll
        for (int ni = 0; ni < 4; ni++)
#pragma unroll
            for (int q = 0; q < 4; q++) acc[mi][ni][q] = 0.f;

    const int gr = rowBase + arow;
    const bool aOK = gr < Rows;
    const size_t aoff = (size_t)(aOK ? gr : 0) * K + ak8;
    const float*  Apf = (const float*)Av + aoff;
    const __half* Aph = (const __half*)Av + aoff;
    const int gcol = colBase + arow;
    const bool bcOK = gcol < Ncols;
    const __half* Btp = Bt + (size_t)(bcOK ? gcol : 0) * K + ak8;
    const size_t SLAB = (size_t)NN * DD;

    float atw[4] = {0.f, 0.f, 0.f, 0.f};
    if (BLEND) { atw[0] = g_attn[0]; atw[1] = g_attn[1]; atw[2] = g_attn[2]; atw[3] = g_attn[3]; }

    const int nk = K >> 4;
    __half2 rah[4];
    uint4 rbh;

    auto load_tile = [&](int kt) {
        const int kb = kt << 4;
        if (AHALF && !BLEND) {
            uint4 q = make_uint4(0u, 0u, 0u, 0u);
            if (aOK) q = __ldg((const uint4*)(Aph + kb));
            *(uint4*)rah = q;
        } else if (AHALF && BLEND) {
            float v[8];
#pragma unroll
            for (int i = 0; i < 8; i++) v[i] = 0.f;
            if (aOK) {
#pragma unroll
                for (int s = 0; s < 4; s++) {
                    uint4 q = __ldg((const uint4*)(Aph + kb + s * SLAB));
                    float2 f0 = __half22float2(*reinterpret_cast<const __half2*>(&q.x));
                    float2 f1 = __half22float2(*reinterpret_cast<const __half2*>(&q.y));
                    float2 f2 = __half22float2(*reinterpret_cast<const __half2*>(&q.z));
                    float2 f3 = __half22float2(*reinterpret_cast<const __half2*>(&q.w));
                    v[0] += atw[s] * f0.x; v[1] += atw[s] * f0.y;
                    v[2] += atw[s] * f1.x; v[3] += atw[s] * f1.y;
                    v[4] += atw[s] * f2.x; v[5] += atw[s] * f2.y;
                    v[6] += atw[s] * f3.x; v[7] += atw[s] * f3.y;
                }
            }
            rah[0] = __floats2half2_rn(v[0], v[1]);
            rah[1] = __floats2half2_rn(v[2], v[3]);
            rah[2] = __floats2half2_rn(v[4], v[5]);
            rah[3] = __floats2half2_rn(v[6], v[7]);
        } else {
            float4 u0 = make_float4(0.f, 0.f, 0.f, 0.f);
            float4 u1 = u0;
            if (aOK) {
                u0 = *(const float4*)(Apf + kb);
                u1 = *(const float4*)(Apf + kb + 4);
            }
            rah[0] = __floats2half2_rn(u0.x, u0.y);
            rah[1] = __floats2half2_rn(u0.z, u0.w);
            rah[2] = __floats2half2_rn(u1.x, u1.y);
            rah[3] = __floats2half2_rn(u1.z, u1.w);
        }
        rbh = make_uint4(0u, 0u, 0u, 0u);
        if (bcOK) rbh = __ldg((const uint4*)(Btp + kb));
    };
    auto store_tile = [&](int buf) {
        *(uint4*)&Ash[buf][arow][ak8] = *(const uint4*)rah;
        *(uint4*)&Bsh[buf][arow][ak8] = rbh;
    };

    load_tile(0);
    store_tile(0);
    __syncthreads();

    for (int kt = 0; kt < nk; kt++) {
        const int buf = kt & 1;
        if (kt + 1 < nk) load_tile(kt + 1);
        const uint32_t* A32 = (const uint32_t*)&Ash[buf][0][0];
        const uint32_t* B32 = (const uint32_t*)&Bsh[buf][0][0];
        uint32_t afr[4][4];
        uint32_t bfr[4][2];
#pragma unroll
        for (int mi = 0; mi < 4; mi++) {
            int row = (wm << 6) + (mi << 4) + g;
            afr[mi][0] = A32[row * 12 + t4];
            afr[mi][1] = A32[(row + 8) * 12 + t4];
            afr[mi][2] = A32[row * 12 + t4 + 4];
            afr[mi][3] = A32[(row + 8) * 12 + t4 + 4];
        }
#pragma unroll
        for (int ni = 0; ni < 4; ni++) {
            int col = (wn << 5) + (ni << 3) + g;
            bfr[ni][0] = B32[col * 12 + t4];
            bfr[ni][1] = B32[col * 12 + t4 + 4];
        }
#pragma unroll
        for (int mi = 0; mi < 4; mi++)
#pragma unroll
            for (int ni = 0; ni < 4; ni++)
                mma_f16(acc[mi][ni], afr[mi], bfr[ni]);
        if (kt + 1 < nk) {
            store_tile(buf ^ 1);
            __syncthreads();
        }
    }

    // ---- epilogue: bias -> C value, store C (fp32 or fp16), fused es/ed dots ----
#pragma unroll
    for (int mi = 0; mi < 4; mi++) {
        int row0 = rowBase + (wm << 6) + (mi << 4) + g;
        int row1 = row0 + 8;
        int orow0 = -1, orow1 = -1;
        if (row0 < Rows) orow0 = permT ? ((row0 % permT) * permN + row0 / permT) : row0;
        if (row1 < Rows) orow1 = permT ? ((row1 % permT) * permN + row1 / permT) : row1;
        float es0 = 0.f, es1 = 0.f, ed0 = 0.f, ed1 = 0.f;
#pragma unroll
        for (int ni = 0; ni < 4; ni++) {
            int col = colBase + (wn << 5) + (ni << 3) + (t4 << 1);
            if (col < Ncols) {
                float bx = 0.f, by = 0.f;
                if (bias) { bx = bias[col]; by = bias[col + 1]; }
                float c00 = acc[mi][ni][0] + bx;
                float c01 = acc[mi][ni][1] + by;
                float c10 = acc[mi][ni][2] + bx;
                float c11 = acc[mi][ni][3] + by;
                if (orow0 >= 0) {
                    if (HALFC) {
                        __half2* cp = (__half2*)((__half*)Cv + (size_t)orow0 * Ncols + col);
                        *cp = __floats2half2_rn(c00, c01);
                    } else {
                        float* cp = (float*)Cv + (size_t)orow0 * Ncols + col;
                        cp[0] = c00;
                        cp[1] = c01;
                    }
                }
                if (orow1 >= 0) {
                    if (HALFC) {
                        __half2* cp = (__half2*)((__half*)Cv + (size_t)orow1 * Ncols + col);
                        *cp = __floats2half2_rn(c10, c11);
                    } else {
                        float* cp = (float*)Cv + (size_t)orow1 * Ncols + col;
                        cp[0] = c10;
                        cp[1] = c11;
                    }
                }
                if (asrc) {
                    float sx = __ldg(asrc + col), sy = __ldg(asrc + col + 1);
                    float dx = __ldg(adst + col), dy = __ldg(adst + col + 1);
                    es0 += c00 * sx + c01 * sy;
                    ed0 += c00 * dx + c01 * dy;
                    es1 += c10 * sx + c11 * sy;
                    ed1 += c10 * dx + c11 * dy;
                }
            }
        }
        if (asrc) {
            es0 += __shfl_xor_sync(0xffffffffu, es0, 1);
            es0 += __shfl_xor_sync(0xffffffffu, es0, 2);
            es1 += __shfl_xor_sync(0xffffffffu, es1, 1);
            es1 += __shfl_xor_sync(0xffffffffu, es1, 2);
            ed0 += __shfl_xor_sync(0xffffffffu, ed0, 1);
            ed0 += __shfl_xor_sync(0xffffffffu, ed0, 2);
            ed1 += __shfl_xor_sync(0xffffffffu, ed1, 1);
            ed1 += __shfl_xor_sync(0xffffffffu, ed1, 2);
            if (t4 == 0) {
                int head = (colBase + (wn << 5)) >> 6;
                if (orow0 >= 0) {
                    atomicAdd(&g_esed[(size_t)orow0 * HEADS + head], es0);
                    atomicAdd(&g_esed[ESZ + (size_t)orow0 * HEADS + head], ed0);
                }
                if (orow1 >= 0) {
                    atomicAdd(&g_esed[(size_t)orow1 * HEADS + head], es1);
                    atomicAdd(&g_esed[ESZ + (size_t)orow1 * HEADS + head], ed1);
                }
            }
        }
    }
}

// ---------------- fused softmax + aggregation, SINGLE PASS: warp per (t, dst) ----------------
// out = ELU( (sum_e w_e * hp[src]) / (z + 1e-16) + bias ),  fp16 in (g_hph), fp16 out.
__global__ void __launch_bounds__(256) agg_kernel(const float* __restrict__ bias,
                                                  __half* __restrict__ out)
{
    int gw = (blockIdx.x * 256 + threadIdx.x) >> 5;
    int lane = threadIdx.x & 31;
    if (gw >= TT * NN) return;
    int t = gw / NN;
    int d = gw - t * NN;
    int base = g_off[d];
    int deg = g_deg[d];
    const size_t tN = (size_t)t * NN;
    int myh = lane >> 3;                   // head of my 8 output cols
    float edh = __ldg(g_esed + ESZ + (size_t)gw * HEADS + myh);

    float z = 0.f;
    float4 a0 = make_float4(0.f, 0.f, 0.f, 0.f);
    float4 a1 = make_float4(0.f, 0.f, 0.f, 0.f);
    for (int j = 0; j < deg; j++) {
        int s = g_srcs[base + j];
        float es = __ldg(g_esed + (tN + s) * HEADS + myh);
        float v = es + edh;
        v = v > 0.f ? v : NEG_SLOPE * v;
        float w = __expf(v);
        z += w;
        const uint4 q = __ldg((const uint4*)(g_hph + (tN + s) * DD + lane * 8));
        float2 f0 = __half22float2(*reinterpret_cast<const __half2*>(&q.x));
        float2 f1 = __half22float2(*reinterpret_cast<const __half2*>(&q.y));
        float2 f2 = __half22float2(*reinterpret_cast<const __half2*>(&q.z));
        float2 f3 = __half22float2(*reinterpret_cast<const __half2*>(&q.w));
        a0.x += w * f0.x; a0.y += w * f0.y;
        a0.z += w * f1.x; a0.w += w * f1.y;
        a1.x += w * f2.x; a1.y += w * f2.y;
        a1.z += w * f3.x; a1.w += w * f3.y;
    }
    float zinv = 1.f / (z + 1e-16f);

    // ---- epilogue: normalize + bias + ELU, single fp16 write ----
    const float4* bp4 = (const float4*)bias + lane * 2;
    float4 b0v = __ldg(bp4), b1v = __ldg(bp4 + 1);
    uint4 o;
    __half2 h0o = __floats2half2_rn(eluf(a0.x * zinv + b0v.x), eluf(a0.y * zinv + b0v.y));
    __half2 h1o = __floats2half2_rn(eluf(a0.z * zinv + b0v.z), eluf(a0.w * zinv + b0v.w));
    __half2 h2o = __floats2half2_rn(eluf(a1.x * zinv + b1v.x), eluf(a1.y * zinv + b1v.y));
    __half2 h3o = __floats2half2_rn(eluf(a1.z * zinv + b1v.z), eluf(a1.w * zinv + b1v.w));
    o.x = *reinterpret_cast<uint32_t*>(&h0o);
    o.y = *reinterpret_cast<uint32_t*>(&h1o);
    o.z = *reinterpret_cast<uint32_t*>(&h2o);
    o.w = *reinterpret_cast<uint32_t*>(&h3o);
    *(uint4*)(out + (size_t)gw * DD + lane * 8) = o;
}

// ---------------- per-t column sums of embs (bufBh, fp16) ----------------
__global__ void __launch_bounds__(256) colsum_kernel()
{
    int t = blockIdx.y;
    int c = threadIdx.x;
    float s = 0.f;
    for (int n = blockIdx.x; n < NN; n += gridDim.x)
        s += __half2float(g_bufBh[((size_t)t * NN + n) * DD + c]);
    atomicAdd(&g_colsum[t * DD + c], s);
}

// ---------------- temporal attention weights (single block) ----------------
__global__ void __launch_bounds__(256) attn_kernel(
    const float* __restrict__ Wq, const float* __restrict__ bq,
    const float* __restrict__ Wk, const float* __restrict__ bk)
{
    __shared__ float mean[TT][DD];
    __shared__ float Kt[TT][DD];
    __shared__ float Qv[DD];
    __shared__ float red[256];
    __shared__ float sc[TT];
    int c = threadIdx.x;
#pragma unroll
    for (int t = 0; t < TT; t++)
        mean[t][c] = g_colsum[t * DD + c] * (1.0f / (float)NN);
    __syncthreads();
#pragma unroll
    for (int t = 0; t < TT; t++) {
        float acc = bk[c];
        for (int f = 0; f < DD; f++) acc += mean[t][f] * Wk[f * DD + c];
        Kt[t][c] = acc;
    }
    {
        float acc = bq[c];
        for (int f = 0; f < DD; f++) acc += mean[TT - 1][f] * Wq[f * DD + c];
        Qv[c] = acc;
    }
    __syncthreads();
    for (int t = 0; t < TT; t++) {
        red[c] = Qv[c] * Kt[t][c];
        __syncthreads();
        for (int off = 128; off > 0; off >>= 1) {
            if (c < off) red[c] += red[c + off];
            __syncthreads();
        }
        if (c == 0) sc[t] = red[0] * (1.0f / 16.0f);   // 1/sqrt(256)
        __syncthreads();
    }
    if (c == 0) {
        float m = fmaxf(fmaxf(sc[0], sc[1]), fmaxf(sc[2], sc[3]));
        float w0 = expf(sc[0] - m), w1 = expf(sc[1] - m);
        float w2 = expf(sc[2] - m), w3 = expf(sc[3] - m);
        float inv = 1.0f / (w0 + w1 + w2 + w3);
        g_attn[0] = w0 * inv; g_attn[1] = w1 * inv;
        g_attn[2] = w2 * inv; g_attn[3] = w3 * inv;
    }
}

// ---------------- launch ----------------
extern "C" void kernel_launch(void* const* d_in, const int* in_sizes, int n_in,
                              void* d_out, int out_size)
{
    const float* x      = (const float*)d_in[0];
    const int*   ei     = (const int*)  d_in[1];
    const float* Wp     = (const float*)d_in[2];
    const float* bp     = (const float*)d_in[3];
    const float* W0     = (const float*)d_in[4];
    const float* a_src0 = (const float*)d_in[5];
    const float* a_dst0 = (const float*)d_in[6];
    const float* b0     = (const float*)d_in[7];
    const float* W1     = (const float*)d_in[8];
    const float* a_src1 = (const float*)d_in[9];
    const float* a_dst1 = (const float*)d_in[10];
    const float* b1     = (const float*)d_in[11];
    const float* Wq     = (const float*)d_in[12];
    const float* bq     = (const float*)d_in[13];
    const float* Wk     = (const float*)d_in[14];
    const float* bk     = (const float*)d_in[15];
    const float* Wv     = (const float*)d_in[16];
    const float* bv     = (const float*)d_in[17];

    float *h0, *esed, *cs;
    __half *hph, *bufAh, *bufBh, *Wpt, *W0t, *W1t, *Wvt;
    int *degp;
    cudaGetSymbolAddress((void**)&h0,    g_h0);
    cudaGetSymbolAddress((void**)&hph,   g_hph);
    cudaGetSymbolAddress((void**)&bufAh, g_bufAh);
    cudaGetSymbolAddress((void**)&bufBh, g_bufBh);
    cudaGetSymbolAddress((void**)&esed,  g_esed);
    cudaGetSymbolAddress((void**)&cs,    g_colsum);
    cudaGetSymbolAddress((void**)&degp,  g_deg);
    cudaGetSymbolAddress((void**)&Wpt,   g_Wpt);
    cudaGetSymbolAddress((void**)&W0t,   g_W0t);
    cudaGetSymbolAddress((void**)&W1t,   g_W1t);
    cudaGetSymbolAddress((void**)&Wvt,   g_Wvt);

    const int rowsTN = TT * NN;            // 120000
    const int edges  = ETOT;               // 270000
    const int gy = (rowsTN + 127) / 128;   // 938
    const int esed4 = 2 * ESZ / 4;         // 480000
    const int wtot = FIN * HH + HH * DD + 2 * DD * DD;   // 163840

    // ---- CSR build (graph shared across t and both layers) ----
    zero_kernel<<<(NN / 4 + 255) / 256, 256>>>((float4*)degp, NN / 4);
    hist_kernel<<<(edges + 255) / 256, 256>>>(ei);
    scan1_kernel<<<NB_SCAN, 256>>>();
    scan2_kernel<<<1, 256>>>();
    scan3_kernel<<<NB_SCAN, 256>>>();
    scatter_kernel<<<(edges + 255) / 256, 256>>>(ei);

    // ---- fp16 transposed weights ----
    wprep_kernel<<<(wtot + 255) / 256, 256>>>(Wp, W0, W1, Wv);

    // ---- h0(t,n) = x[n,t] @ Wp + bp  (64-wide, bias folded here, perm output) ----
    gemm_f16<0, 0, 0><<<dim3(1, gy), 256>>>(x, Wpt, bp, h0, rowsTN, FIN, HH,
                                            TT, NN, nullptr, nullptr);

    // ---- GAT layer 0: hp = h0 @ W0 (K=64, fp16 out), es/ed fused ----
    zero_kernel<<<(esed4 + 255) / 256, 256>>>((float4*)esed, esed4);
    gemm_f16<0, 0, 1><<<dim3(2, gy), 256>>>(h0, W0t, nullptr, hph, rowsTN, HH, DD,
                                            0, 0, a_src0, a_dst0);
    agg_kernel<<<(rowsTN + 7) / 8, 256>>>(b0, bufAh);

    // ---- GAT layer 1 (fp16 A in, fp16 hp out) ----
    zero_kernel<<<(esed4 + 255) / 256, 256>>>((float4*)esed, esed4);
    gemm_f16<0, 1, 1><<<dim3(2, gy), 256>>>(bufAh, W1t, nullptr, hph, rowsTN, DD, DD,
                                            0, 0, a_src1, a_dst1);
    agg_kernel<<<(rowsTN + 7) / 8, 256>>>(b1, bufBh);

    // ---- temporal attention ----
    zero_kernel<<<1, 256>>>((float4*)cs, TT * DD / 4);
    colsum_kernel<<<dim3(128, TT), 256>>>();
    attn_kernel<<<1, 256>>>(Wq, bq, Wk, bk);

    // ---- out = (sum_t attn[t] * embs_t) @ Wv + bv  (blend fused, fp16 A) ----
    gemm_f16<1, 1, 0><<<dim3(2, (NN + 127) / 128), 256>>>(bufBh, Wvt, bv, (float*)d_out,
                                                          NN, DD, DD, 0, 0, nullptr, nullptr);
}